// round 1
// baseline (speedup 1.0000x reference)
#include <cuda_runtime.h>

#define D_MODEL  1024
#define N_HEADS  16
#define HEAD_DIM 64
#define SEQ_L    2048
#define BATCH    4
#define WINDOW   512

// Scratch (static device globals: allocation-guard safe)
__device__ float g_q[BATCH * SEQ_L * D_MODEL];
__device__ float g_k[BATCH * SEQ_L * D_MODEL];
__device__ float g_v[BATCH * SEQ_L * D_MODEL];
__device__ float g_att[BATCH * SEQ_L * D_MODEL];

// ---------------------------------------------------------------------------
// C[m][n] = sum_k A[m][k] * W[n][k] + bias[n]   (torch Linear: x @ W.T + b)
// A: [M,K] row-major, W: [N,K] row-major. M,N,K multiples of 128/128/8.
// 128x128 tile, BK=8, 256 threads, 8x8 microtile (split 4+4 for bank-free LDS.128)
// ---------------------------------------------------------------------------
__global__ __launch_bounds__(256) void sgemm_nt_bias(
    const float* __restrict__ A, const float* __restrict__ W,
    const float* __restrict__ bias, float* __restrict__ C,
    int M, int N, int K)
{
    __shared__ float As[8][128];
    __shared__ float Ws[8][128];

    const int tid = threadIdx.x;
    const int tx  = tid & 15;
    const int ty  = tid >> 4;
    const int m0  = blockIdx.y * 128;
    const int n0  = blockIdx.x * 128;

    const int lRow = tid >> 1;          // 0..127
    const int lCol = (tid & 1) * 4;     // 0 or 4

    const float* Aptr = A + (size_t)(m0 + lRow) * K + lCol;
    const float* Wptr = W + (size_t)(n0 + lRow) * K + lCol;

    float acc[8][8];
#pragma unroll
    for (int i = 0; i < 8; ++i)
#pragma unroll
        for (int j = 0; j < 8; ++j) acc[i][j] = 0.f;

    for (int k0 = 0; k0 < K; k0 += 8) {
        float4 av = *(const float4*)(Aptr + k0);
        float4 wv = *(const float4*)(Wptr + k0);
        __syncthreads();
        As[lCol + 0][lRow] = av.x; As[lCol + 1][lRow] = av.y;
        As[lCol + 2][lRow] = av.z; As[lCol + 3][lRow] = av.w;
        Ws[lCol + 0][lRow] = wv.x; Ws[lCol + 1][lRow] = wv.y;
        Ws[lCol + 2][lRow] = wv.z; Ws[lCol + 3][lRow] = wv.w;
        __syncthreads();
#pragma unroll
        for (int kk = 0; kk < 8; ++kk) {
            float a[8], w[8];
            *(float4*)&a[0] = *(float4*)&As[kk][ty * 4];
            *(float4*)&a[4] = *(float4*)&As[kk][64 + ty * 4];
            *(float4*)&w[0] = *(float4*)&Ws[kk][tx * 4];
            *(float4*)&w[4] = *(float4*)&Ws[kk][64 + tx * 4];
#pragma unroll
            for (int i = 0; i < 8; ++i)
#pragma unroll
                for (int j = 0; j < 8; ++j)
                    acc[i][j] += a[i] * w[j];
        }
    }

#pragma unroll
    for (int i = 0; i < 8; ++i) {
        const int r = m0 + ((i < 4) ? (ty * 4 + i) : (64 + ty * 4 + (i - 4)));
#pragma unroll
        for (int jh = 0; jh < 2; ++jh) {
            const int c = n0 + ((jh == 0) ? (tx * 4) : (64 + tx * 4));
            float4 bv = *(const float4*)&bias[c];
            float4 o;
            o.x = acc[i][jh * 4 + 0] + bv.x;
            o.y = acc[i][jh * 4 + 1] + bv.y;
            o.z = acc[i][jh * 4 + 2] + bv.z;
            o.w = acc[i][jh * 4 + 3] + bv.w;
            *(float4*)&C[(size_t)r * N + c] = o;
        }
    }
}

// ---------------------------------------------------------------------------
// Flash attention with ALiBi + causal + sliding-window(512) mask.
// Q/K/V layout: [B, L, H, d] (i.e., [B, L, D] with heads packed in D).
// Block: 256 threads, 64 queries x full head. Key tiles of 64 over the window.
// Dynamic smem: QsT[64][68] + KsT[64][68] (reused as PsT) + Vs[64][64]
// ---------------------------------------------------------------------------
#define SP 68   // padded stride for transposed tiles
#define ATTN_SMEM_BYTES ((64 * SP * 2 + 64 * 64) * 4)

__global__ __launch_bounds__(256) void attn_alibi_kernel(
    const float* __restrict__ Q, const float* __restrict__ K,
    const float* __restrict__ V, const unsigned char* __restrict__ pad,
    float* __restrict__ O)
{
    const int qt = blockIdx.x;           // query tile (64 rows)
    const int bh = blockIdx.y;
    const int b  = bh >> 4;              // / N_HEADS
    const int h  = bh & 15;

    extern __shared__ float sm[];
    float* QsT = sm;                     // [64 d][SP q]
    float* KsT = sm + 64 * SP;           // [64 d][SP k]   (reused as PsT[k][q])
    float* Vs  = sm + 2 * 64 * SP;       // [64 k][64 d]

    __shared__ float red[64][17];
    __shared__ float m_s[64], l_s[64], sc_s[64];

    const int tid = threadIdx.x;
    const int tx  = tid & 15;
    const int ty  = tid >> 4;

    const float slope = exp2f(-0.5f * (float)(h + 1));  // 16 heads: 2^(-(h+1)/2)

    const float* Qb = Q + ((size_t)b * SEQ_L) * D_MODEL + h * HEAD_DIM;
    const float* Kb = K + ((size_t)b * SEQ_L) * D_MODEL + h * HEAD_DIM;
    const float* Vb = V + ((size_t)b * SEQ_L) * D_MODEL + h * HEAD_DIM;
    const unsigned char* padb = pad + (size_t)b * SEQ_L;

    // Load Q tile transposed
    for (int idx = tid; idx < 64 * 64; idx += 256) {
        const int q = idx >> 6, dd = idx & 63;
        QsT[dd * SP + q] = Qb[(size_t)(qt * 64 + q) * D_MODEL + dd];
    }
    if (tid < 64) { m_s[tid] = -1e30f; l_s[tid] = 0.f; }

    float Oacc[4][4];
#pragma unroll
    for (int i = 0; i < 4; ++i)
#pragma unroll
        for (int j = 0; j < 4; ++j) Oacc[i][j] = 0.f;

    const int kt_lo = (qt >= 8) ? (qt - 8) : 0;
    for (int kt = kt_lo; kt <= qt; ++kt) {
        __syncthreads();   // Q ready / previous tile fully consumed
        for (int idx = tid; idx < 64 * 64; idx += 256) {
            const int r = idx >> 6, dd = idx & 63;
            const float kvK = Kb[(size_t)(kt * 64 + r) * D_MODEL + dd];
            const float kvV = Vb[(size_t)(kt * 64 + r) * D_MODEL + dd];
            KsT[dd * SP + r] = kvK;
            Vs[r * 64 + dd]  = kvV;
        }
        __syncthreads();

        // S = Q . K^T  (per-thread 4x4)
        float S[4][4];
#pragma unroll
        for (int i = 0; i < 4; ++i)
#pragma unroll
            for (int j = 0; j < 4; ++j) S[i][j] = 0.f;
#pragma unroll 8
        for (int dd = 0; dd < 64; ++dd) {
            float a[4], w[4];
            *(float4*)a = *(float4*)&QsT[dd * SP + ty * 4];
            *(float4*)w = *(float4*)&KsT[dd * SP + tx * 4];
#pragma unroll
            for (int i = 0; i < 4; ++i)
#pragma unroll
                for (int j = 0; j < 4; ++j)
                    S[i][j] += a[i] * w[j];
        }

        // scale + ALiBi + causal/window/padding mask; per-thread row maxes
#pragma unroll
        for (int i = 0; i < 4; ++i) {
            const int gi = qt * 64 + ty * 4 + i;
            float rmax = -1e30f;
#pragma unroll
            for (int j = 0; j < 4; ++j) {
                const int gj = kt * 64 + tx * 4 + j;
                float s;
                if (gj <= gi && gj + WINDOW >= gi && !padb[gj])
                    s = S[i][j] * 0.125f + slope * (float)(gj - gi);
                else
                    s = -1e30f;
                S[i][j] = s;
                rmax = fmaxf(rmax, s);
            }
            red[ty * 4 + i][tx] = rmax;
        }
        __syncthreads();

        if (tid < 64) {
            float mt = red[tid][0];
#pragma unroll
            for (int t = 1; t < 16; ++t) mt = fmaxf(mt, red[tid][t]);
            const float mo = m_s[tid];
            const float mn = fmaxf(mo, mt);
            const float sc = __expf(mo - mn);   // mo=mn=-1e30 -> 1, harmless (l=0)
            m_s[tid]  = mn;
            sc_s[tid] = sc;
            l_s[tid] *= sc;
        }
        __syncthreads();

        // P = exp(S - m); rescale O; partial row sums; write PsT into KsT buf
#pragma unroll
        for (int i = 0; i < 4; ++i) {
            const float mn = m_s[ty * 4 + i];
            float rs = 0.f;
#pragma unroll
            for (int j = 0; j < 4; ++j) {
                float p = (S[i][j] < -1e29f) ? 0.f : __expf(S[i][j] - mn);
                S[i][j] = p;
                rs += p;
            }
            red[ty * 4 + i][tx] = rs;
            const float sc = sc_s[ty * 4 + i];
#pragma unroll
            for (int j = 0; j < 4; ++j) Oacc[i][j] *= sc;
        }
#pragma unroll
        for (int j = 0; j < 4; ++j) {
            float4 pv = make_float4(S[0][j], S[1][j], S[2][j], S[3][j]);
            *(float4*)&KsT[(tx * 4 + j) * SP + ty * 4] = pv;   // PsT[k][q]
        }
        __syncthreads();

        if (tid < 64) {
            float s = 0.f;
#pragma unroll
            for (int t = 0; t < 16; ++t) s += red[tid][t];
            l_s[tid] += s;
        }

        // O += P . V
#pragma unroll 8
        for (int kk = 0; kk < 64; ++kk) {
            float a[4], w[4];
            *(float4*)a = *(float4*)&KsT[kk * SP + ty * 4];
            *(float4*)w = *(float4*)&Vs[kk * 64 + tx * 4];
#pragma unroll
            for (int i = 0; i < 4; ++i)
#pragma unroll
                for (int j = 0; j < 4; ++j)
                    Oacc[i][j] += a[i] * w[j];
        }
    }
    __syncthreads();   // l_s final

#pragma unroll
    for (int i = 0; i < 4; ++i) {
        const int gi = qt * 64 + ty * 4 + i;
        const float inv = 1.f / l_s[ty * 4 + i];
        float4 o = make_float4(Oacc[i][0] * inv, Oacc[i][1] * inv,
                               Oacc[i][2] * inv, Oacc[i][3] * inv);
        *(float4*)&O[((size_t)b * SEQ_L + gi) * D_MODEL + h * HEAD_DIM + tx * 4] = o;
    }
}

// ---------------------------------------------------------------------------
// Launch: 3 projection GEMMs -> attention -> output GEMM
// Inputs (metadata order): x, key_padding_mask, Wq, bq, Wk, bk, Wv, bv, Wo, bo
// ---------------------------------------------------------------------------
extern "C" void kernel_launch(void* const* d_in, const int* in_sizes, int n_in,
                              void* d_out, int out_size)
{
    const float* x  = (const float*)d_in[0];
    const unsigned char* pad = (const unsigned char*)d_in[1];
    const float* Wq = (const float*)d_in[2];
    const float* bq = (const float*)d_in[3];
    const float* Wk = (const float*)d_in[4];
    const float* bk = (const float*)d_in[5];
    const float* Wv = (const float*)d_in[6];
    const float* bv = (const float*)d_in[7];
    const float* Wo = (const float*)d_in[8];
    const float* bo = (const float*)d_in[9];
    float* out = (float*)d_out;

    float *q, *k, *v, *att;
    cudaGetSymbolAddress((void**)&q,   g_q);
    cudaGetSymbolAddress((void**)&k,   g_k);
    cudaGetSymbolAddress((void**)&v,   g_v);
    cudaGetSymbolAddress((void**)&att, g_att);

    cudaFuncSetAttribute(attn_alibi_kernel,
                         cudaFuncAttributeMaxDynamicSharedMemorySize,
                         ATTN_SMEM_BYTES);

    const int M = BATCH * SEQ_L;           // 8192
    dim3 ggrid(D_MODEL / 128, M / 128);    // (8, 64)
    sgemm_nt_bias<<<ggrid, 256>>>(x, Wq, bq, q, M, D_MODEL, D_MODEL);
    sgemm_nt_bias<<<ggrid, 256>>>(x, Wk, bk, k, M, D_MODEL, D_MODEL);
    sgemm_nt_bias<<<ggrid, 256>>>(x, Wv, bv, v, M, D_MODEL, D_MODEL);

    dim3 agrid(SEQ_L / 64, BATCH * N_HEADS);   // (32, 64)
    attn_alibi_kernel<<<agrid, 256, ATTN_SMEM_BYTES>>>(q, k, v, pad, att);

    sgemm_nt_bias<<<ggrid, 256>>>(att, Wo, bo, out, M, D_MODEL, D_MODEL);
}

// round 2
// speedup vs baseline: 1.6386x; 1.6386x over previous
#include <cuda_runtime.h>
#include <cstdint>

#define D_MODEL  1024
#define N_HEADS  16
#define HEAD_DIM 64
#define SEQ_L    2048
#define BATCH    4
#define WINDOW   512

// Scratch (static device globals: allocation-guard safe)
__device__ float g_q[BATCH * SEQ_L * D_MODEL];
__device__ float g_k[BATCH * SEQ_L * D_MODEL];
__device__ float g_v[BATCH * SEQ_L * D_MODEL];
__device__ float g_att[BATCH * SEQ_L * D_MODEL];

// ---------------------------------------------------------------------------
// tf32 tensor-core GEMM: C[m][n] = sum_k A[m][k]*W[n][k] + bias[n]
// A: [M,K] row-major, W: [N,K] row-major (torch Linear x @ W.T + b).
// Block tile 128x128, BK=32, 256 threads = 8 warps (2 M x 4 N), warp tile 64x32.
// mma.sync.aligned.m16n8k8.row.col.f32.tf32.tf32.f32, fp32 accumulate.
// smem XOR swizzle: element [row][k] at row*32 + (k ^ ((row&7)<<2))
//   -> all fragment LDS.32 loads are 32-bank conflict-free.
// ---------------------------------------------------------------------------
__device__ __forceinline__ uint32_t f2tf32(float f) {
    uint32_t u;
    asm("cvt.rna.tf32.f32 %0, %1;" : "=r"(u) : "f"(f));
    return u;
}

__global__ __launch_bounds__(256) void gemm_tf32_nt_bias(
    const float* __restrict__ A, const float* __restrict__ W,
    const float* __restrict__ bias, float* __restrict__ C,
    int M, int N, int K)
{
    __shared__ uint32_t As[128 * 32];
    __shared__ uint32_t Bs[128 * 32];

    const int tid    = threadIdx.x;
    const int warpId = tid >> 5;
    const int lane   = tid & 31;
    const int r      = lane >> 2;   // 0..7
    const int c      = lane & 3;    // 0..3
    const int warpM  = (warpId >> 2) * 64;
    const int warpN  = (warpId & 3) * 32;
    const int m0     = blockIdx.y * 128;
    const int n0     = blockIdx.x * 128;

    // global->smem mapping: thread covers row tid/2, 16 consecutive k
    const int gRow = tid >> 1;
    const int gK   = (tid & 1) * 16;
    const float* Ag = A + (size_t)(m0 + gRow) * K + gK;
    const float* Wg = W + (size_t)(n0 + gRow) * K + gK;
    const int swr   = (gRow & 7) << 2;
    uint32_t* AsW = As + gRow * 32;
    uint32_t* BsW = Bs + gRow * 32;

    float acc[4][4][4];
#pragma unroll
    for (int mt = 0; mt < 4; ++mt)
#pragma unroll
        for (int nt = 0; nt < 4; ++nt)
#pragma unroll
            for (int q = 0; q < 4; ++q) acc[mt][nt][q] = 0.f;

    float4 pa[4], pw[4];
#pragma unroll
    for (int i = 0; i < 4; ++i) {
        pa[i] = *(const float4*)(Ag + i * 4);
        pw[i] = *(const float4*)(Wg + i * 4);
    }

    const int rsw = r << 2;   // row&7 == r for all fragment rows (16-multiples)

    for (int k0 = 0; k0 < K; k0 += 32) {
        __syncthreads();
#pragma unroll
        for (int i = 0; i < 4; ++i) {
            const int sc = (gK + i * 4) ^ swr;
            uint4 av = make_uint4(f2tf32(pa[i].x), f2tf32(pa[i].y),
                                  f2tf32(pa[i].z), f2tf32(pa[i].w));
            uint4 wv = make_uint4(f2tf32(pw[i].x), f2tf32(pw[i].y),
                                  f2tf32(pw[i].z), f2tf32(pw[i].w));
            *(uint4*)(AsW + sc) = av;
            *(uint4*)(BsW + sc) = wv;
        }
        __syncthreads();

        if (k0 + 32 < K) {
#pragma unroll
            for (int i = 0; i < 4; ++i) {
                pa[i] = *(const float4*)(Ag + k0 + 32 + i * 4);
                pw[i] = *(const float4*)(Wg + k0 + 32 + i * 4);
            }
        }

#pragma unroll
        for (int ks = 0; ks < 4; ++ks) {
            const int col0 = (8 * ks + c) ^ rsw;
            const int col1 = (8 * ks + c + 4) ^ rsw;

            uint32_t af[4][4];
#pragma unroll
            for (int mt = 0; mt < 4; ++mt) {
                const int base = (warpM + 16 * mt + r) * 32;
                af[mt][0] = As[base + col0];
                af[mt][1] = As[base + 256 + col0];
                af[mt][2] = As[base + col1];
                af[mt][3] = As[base + 256 + col1];
            }
#pragma unroll
            for (int nt = 0; nt < 4; ++nt) {
                const int nbase = (warpN + 8 * nt + r) * 32;
                const uint32_t b0 = Bs[nbase + col0];
                const uint32_t b1 = Bs[nbase + col1];
#pragma unroll
                for (int mt = 0; mt < 4; ++mt) {
                    asm volatile(
                        "mma.sync.aligned.m16n8k8.row.col.f32.tf32.tf32.f32 "
                        "{%0,%1,%2,%3}, {%4,%5,%6,%7}, {%8,%9}, {%0,%1,%2,%3};"
                        : "+f"(acc[mt][nt][0]), "+f"(acc[mt][nt][1]),
                          "+f"(acc[mt][nt][2]), "+f"(acc[mt][nt][3])
                        : "r"(af[mt][0]), "r"(af[mt][1]),
                          "r"(af[mt][2]), "r"(af[mt][3]),
                          "r"(b0), "r"(b1));
                }
            }
        }
    }

    // Epilogue: c0/c1 at (r, 2c..2c+1), c2/c3 at (r+8, same cols)
#pragma unroll
    for (int nt = 0; nt < 4; ++nt) {
        const int col = n0 + warpN + 8 * nt + 2 * c;
        const float2 bv = *(const float2*)&bias[col];
#pragma unroll
        for (int mt = 0; mt < 4; ++mt) {
            const int row = m0 + warpM + 16 * mt + r;
            float2 o0 = make_float2(acc[mt][nt][0] + bv.x, acc[mt][nt][1] + bv.y);
            float2 o1 = make_float2(acc[mt][nt][2] + bv.x, acc[mt][nt][3] + bv.y);
            *(float2*)&C[(size_t)row * N + col]       = o0;
            *(float2*)&C[(size_t)(row + 8) * N + col] = o1;
        }
    }
}

// ---------------------------------------------------------------------------
// Flash attention with ALiBi + causal + sliding-window(512) mask. (unchanged)
// ---------------------------------------------------------------------------
#define SP 68
#define ATTN_SMEM_BYTES ((64 * SP * 2 + 64 * 64) * 4)

__global__ __launch_bounds__(256) void attn_alibi_kernel(
    const float* __restrict__ Q, const float* __restrict__ K,
    const float* __restrict__ V, const unsigned char* __restrict__ pad,
    float* __restrict__ O)
{
    const int qt = blockIdx.x;
    const int bh = blockIdx.y;
    const int b  = bh >> 4;
    const int h  = bh & 15;

    extern __shared__ float sm[];
    float* QsT = sm;
    float* KsT = sm + 64 * SP;
    float* Vs  = sm + 2 * 64 * SP;

    __shared__ float red[64][17];
    __shared__ float m_s[64], l_s[64], sc_s[64];

    const int tid = threadIdx.x;
    const int tx  = tid & 15;
    const int ty  = tid >> 4;

    const float slope = exp2f(-0.5f * (float)(h + 1));

    const float* Qb = Q + ((size_t)b * SEQ_L) * D_MODEL + h * HEAD_DIM;
    const float* Kb = K + ((size_t)b * SEQ_L) * D_MODEL + h * HEAD_DIM;
    const float* Vb = V + ((size_t)b * SEQ_L) * D_MODEL + h * HEAD_DIM;
    const unsigned char* padb = pad + (size_t)b * SEQ_L;

    for (int idx = tid; idx < 64 * 64; idx += 256) {
        const int q = idx >> 6, dd = idx & 63;
        QsT[dd * SP + q] = Qb[(size_t)(qt * 64 + q) * D_MODEL + dd];
    }
    if (tid < 64) { m_s[tid] = -1e30f; l_s[tid] = 0.f; }

    float Oacc[4][4];
#pragma unroll
    for (int i = 0; i < 4; ++i)
#pragma unroll
        for (int j = 0; j < 4; ++j) Oacc[i][j] = 0.f;

    const int kt_lo = (qt >= 8) ? (qt - 8) : 0;
    for (int kt = kt_lo; kt <= qt; ++kt) {
        __syncthreads();
        for (int idx = tid; idx < 64 * 64; idx += 256) {
            const int rr = idx >> 6, dd = idx & 63;
            KsT[dd * SP + rr] = Kb[(size_t)(kt * 64 + rr) * D_MODEL + dd];
            Vs[rr * 64 + dd]  = Vb[(size_t)(kt * 64 + rr) * D_MODEL + dd];
        }
        __syncthreads();

        float S[4][4];
#pragma unroll
        for (int i = 0; i < 4; ++i)
#pragma unroll
            for (int j = 0; j < 4; ++j) S[i][j] = 0.f;
#pragma unroll 8
        for (int dd = 0; dd < 64; ++dd) {
            float a[4], w[4];
            *(float4*)a = *(float4*)&QsT[dd * SP + ty * 4];
            *(float4*)w = *(float4*)&KsT[dd * SP + tx * 4];
#pragma unroll
            for (int i = 0; i < 4; ++i)
#pragma unroll
                for (int j = 0; j < 4; ++j)
                    S[i][j] += a[i] * w[j];
        }

#pragma unroll
        for (int i = 0; i < 4; ++i) {
            const int gi = qt * 64 + ty * 4 + i;
            float rmax = -1e30f;
#pragma unroll
            for (int j = 0; j < 4; ++j) {
                const int gj = kt * 64 + tx * 4 + j;
                float s;
                if (gj <= gi && gj + WINDOW >= gi && !padb[gj])
                    s = S[i][j] * 0.125f + slope * (float)(gj - gi);
                else
                    s = -1e30f;
                S[i][j] = s;
                rmax = fmaxf(rmax, s);
            }
            red[ty * 4 + i][tx] = rmax;
        }
        __syncthreads();

        if (tid < 64) {
            float mt = red[tid][0];
#pragma unroll
            for (int t = 1; t < 16; ++t) mt = fmaxf(mt, red[tid][t]);
            const float mo = m_s[tid];
            const float mn = fmaxf(mo, mt);
            const float sc = __expf(mo - mn);
            m_s[tid]  = mn;
            sc_s[tid] = sc;
            l_s[tid] *= sc;
        }
        __syncthreads();

#pragma unroll
        for (int i = 0; i < 4; ++i) {
            const float mn = m_s[ty * 4 + i];
            float rs = 0.f;
#pragma unroll
            for (int j = 0; j < 4; ++j) {
                float p = (S[i][j] < -1e29f) ? 0.f : __expf(S[i][j] - mn);
                S[i][j] = p;
                rs += p;
            }
            red[ty * 4 + i][tx] = rs;
            const float sc = sc_s[ty * 4 + i];
#pragma unroll
            for (int j = 0; j < 4; ++j) Oacc[i][j] *= sc;
        }
#pragma unroll
        for (int j = 0; j < 4; ++j) {
            float4 pv = make_float4(S[0][j], S[1][j], S[2][j], S[3][j]);
            *(float4*)&KsT[(tx * 4 + j) * SP + ty * 4] = pv;
        }
        __syncthreads();

        if (tid < 64) {
            float s = 0.f;
#pragma unroll
            for (int t = 0; t < 16; ++t) s += red[tid][t];
            l_s[tid] += s;
        }

#pragma unroll 8
        for (int kk = 0; kk < 64; ++kk) {
            float a[4], w[4];
            *(float4*)a = *(float4*)&KsT[kk * SP + ty * 4];
            *(float4*)w = *(float4*)&Vs[kk * 64 + tx * 4];
#pragma unroll
            for (int i = 0; i < 4; ++i)
#pragma unroll
                for (int j = 0; j < 4; ++j)
                    Oacc[i][j] += a[i] * w[j];
        }
    }
    __syncthreads();

#pragma unroll
    for (int i = 0; i < 4; ++i) {
        const int gi = qt * 64 + ty * 4 + i;
        const float inv = 1.f / l_s[ty * 4 + i];
        float4 o = make_float4(Oacc[i][0] * inv, Oacc[i][1] * inv,
                               Oacc[i][2] * inv, Oacc[i][3] * inv);
        *(float4*)&O[((size_t)b * SEQ_L + gi) * D_MODEL + h * HEAD_DIM + tx * 4] = o;
    }
}

// ---------------------------------------------------------------------------
extern "C" void kernel_launch(void* const* d_in, const int* in_sizes, int n_in,
                              void* d_out, int out_size)
{
    const float* x  = (const float*)d_in[0];
    const unsigned char* pad = (const unsigned char*)d_in[1];
    const float* Wq = (const float*)d_in[2];
    const float* bq = (const float*)d_in[3];
    const float* Wk = (const float*)d_in[4];
    const float* bk = (const float*)d_in[5];
    const float* Wv = (const float*)d_in[6];
    const float* bv = (const float*)d_in[7];
    const float* Wo = (const float*)d_in[8];
    const float* bo = (const float*)d_in[9];
    float* out = (float*)d_out;

    float *q, *k, *v, *att;
    cudaGetSymbolAddress((void**)&q,   g_q);
    cudaGetSymbolAddress((void**)&k,   g_k);
    cudaGetSymbolAddress((void**)&v,   g_v);
    cudaGetSymbolAddress((void**)&att, g_att);

    cudaFuncSetAttribute(attn_alibi_kernel,
                         cudaFuncAttributeMaxDynamicSharedMemorySize,
                         ATTN_SMEM_BYTES);

    const int M = BATCH * SEQ_L;           // 8192
    dim3 ggrid(D_MODEL / 128, M / 128);    // (8, 64)
    gemm_tf32_nt_bias<<<ggrid, 256>>>(x, Wq, bq, q, M, D_MODEL, D_MODEL);
    gemm_tf32_nt_bias<<<ggrid, 256>>>(x, Wk, bk, k, M, D_MODEL, D_MODEL);
    gemm_tf32_nt_bias<<<ggrid, 256>>>(x, Wv, bv, v, M, D_MODEL, D_MODEL);

    dim3 agrid(SEQ_L / 64, BATCH * N_HEADS);   // (32, 64)
    attn_alibi_kernel<<<agrid, 256, ATTN_SMEM_BYTES>>>(q, k, v, pad, att);

    gemm_tf32_nt_bias<<<ggrid, 256>>>(att, Wo, bo, out, M, D_MODEL, D_MODEL);
}

// round 3
// speedup vs baseline: 1.7984x; 1.0975x over previous
#include <cuda_runtime.h>
#include <cstdint>

#define D_MODEL  1024
#define N_HEADS  16
#define HEAD_DIM 64
#define SEQ_L    2048
#define BATCH    4
#define WINDOW   512

__device__ float g_q[BATCH * SEQ_L * D_MODEL];
__device__ float g_k[BATCH * SEQ_L * D_MODEL];
__device__ float g_v[BATCH * SEQ_L * D_MODEL];
__device__ float g_att[BATCH * SEQ_L * D_MODEL];

__device__ __forceinline__ uint32_t f2tf32(float f) {
    uint32_t u;
    asm("cvt.rna.tf32.f32 %0, %1;" : "=r"(u) : "f"(f));
    return u;
}
__device__ __forceinline__ void split_tf32(float x, uint32_t& hi, uint32_t& lo) {
    hi = f2tf32(x);
    lo = f2tf32(x - __uint_as_float(hi));
}
__device__ __forceinline__ void mma_tf32(float* d, const uint32_t* a,
                                         uint32_t b0, uint32_t b1) {
    asm volatile(
        "mma.sync.aligned.m16n8k8.row.col.f32.tf32.tf32.f32 "
        "{%0,%1,%2,%3}, {%4,%5,%6,%7}, {%8,%9}, {%0,%1,%2,%3};"
        : "+f"(d[0]), "+f"(d[1]), "+f"(d[2]), "+f"(d[3])
        : "r"(a[0]), "r"(a[1]), "r"(a[2]), "r"(a[3]), "r"(b0), "r"(b1));
}

// ---------------------------------------------------------------------------
// tf32 tensor-core GEMM (unchanged from round 2)
// ---------------------------------------------------------------------------
__global__ __launch_bounds__(256) void gemm_tf32_nt_bias(
    const float* __restrict__ A, const float* __restrict__ W,
    const float* __restrict__ bias, float* __restrict__ C,
    int M, int N, int K)
{
    __shared__ uint32_t As[128 * 32];
    __shared__ uint32_t Bs[128 * 32];

    const int tid    = threadIdx.x;
    const int warpId = tid >> 5;
    const int lane   = tid & 31;
    const int r      = lane >> 2;
    const int c      = lane & 3;
    const int warpM  = (warpId >> 2) * 64;
    const int warpN  = (warpId & 3) * 32;
    const int m0     = blockIdx.y * 128;
    const int n0     = blockIdx.x * 128;

    const int gRow = tid >> 1;
    const int gK   = (tid & 1) * 16;
    const float* Ag = A + (size_t)(m0 + gRow) * K + gK;
    const float* Wg = W + (size_t)(n0 + gRow) * K + gK;
    const int swr   = (gRow & 7) << 2;
    uint32_t* AsW = As + gRow * 32;
    uint32_t* BsW = Bs + gRow * 32;

    float acc[4][4][4];
#pragma unroll
    for (int mt = 0; mt < 4; ++mt)
#pragma unroll
        for (int nt = 0; nt < 4; ++nt)
#pragma unroll
            for (int q = 0; q < 4; ++q) acc[mt][nt][q] = 0.f;

    float4 pa[4], pw[4];
#pragma unroll
    for (int i = 0; i < 4; ++i) {
        pa[i] = *(const float4*)(Ag + i * 4);
        pw[i] = *(const float4*)(Wg + i * 4);
    }

    const int rsw = r << 2;

    for (int k0 = 0; k0 < K; k0 += 32) {
        __syncthreads();
#pragma unroll
        for (int i = 0; i < 4; ++i) {
            const int sc = (gK + i * 4) ^ swr;
            uint4 av = make_uint4(f2tf32(pa[i].x), f2tf32(pa[i].y),
                                  f2tf32(pa[i].z), f2tf32(pa[i].w));
            uint4 wv = make_uint4(f2tf32(pw[i].x), f2tf32(pw[i].y),
                                  f2tf32(pw[i].z), f2tf32(pw[i].w));
            *(uint4*)(AsW + sc) = av;
            *(uint4*)(BsW + sc) = wv;
        }
        __syncthreads();

        if (k0 + 32 < K) {
#pragma unroll
            for (int i = 0; i < 4; ++i) {
                pa[i] = *(const float4*)(Ag + k0 + 32 + i * 4);
                pw[i] = *(const float4*)(Wg + k0 + 32 + i * 4);
            }
        }

#pragma unroll
        for (int ks = 0; ks < 4; ++ks) {
            const int col0 = (8 * ks + c) ^ rsw;
            const int col1 = (8 * ks + c + 4) ^ rsw;

            uint32_t af[4][4];
#pragma unroll
            for (int mt = 0; mt < 4; ++mt) {
                const int base = (warpM + 16 * mt + r) * 32;
                af[mt][0] = As[base + col0];
                af[mt][1] = As[base + 256 + col0];
                af[mt][2] = As[base + col1];
                af[mt][3] = As[base + 256 + col1];
            }
#pragma unroll
            for (int nt = 0; nt < 4; ++nt) {
                const int nbase = (warpN + 8 * nt + r) * 32;
                const uint32_t b0 = Bs[nbase + col0];
                const uint32_t b1 = Bs[nbase + col1];
#pragma unroll
                for (int mt = 0; mt < 4; ++mt)
                    mma_tf32(acc[mt][nt], af[mt], b0, b1);
            }
        }
    }

#pragma unroll
    for (int nt = 0; nt < 4; ++nt) {
        const int col = n0 + warpN + 8 * nt + 2 * c;
        const float2 bv = *(const float2*)&bias[col];
#pragma unroll
        for (int mt = 0; mt < 4; ++mt) {
            const int row = m0 + warpM + 16 * mt + r;
            float2 o0 = make_float2(acc[mt][nt][0] + bv.x, acc[mt][nt][1] + bv.y);
            float2 o1 = make_float2(acc[mt][nt][2] + bv.x, acc[mt][nt][3] + bv.y);
            *(float2*)&C[(size_t)row * N + col]       = o0;
            *(float2*)&C[(size_t)(row + 8) * N + col] = o1;
        }
    }
}

// ---------------------------------------------------------------------------
// Flash attention, tensor-core tf32x2 (3-mma split => fp32-accurate).
// Block: 64 queries, 256 threads = 8 warps: wq = warp>>1 (16 q-rows each),
// wk = warp&1 (32-key / 32-d half). Key tiles of 64 over 512-window.
// smem strides: Q/K/P at 68 (banks 4r+c), V at 72 (banks 8c+r) -> conflict-free.
// ---------------------------------------------------------------------------
#define SQ 68
#define SV 72
#define ATTN_WORDS (4 * 64 * SQ + 2 * 64 * SV)
#define ATTN_SMEM_BYTES (ATTN_WORDS * 4)

__global__ __launch_bounds__(256) void attn_alibi_mma(
    const float* __restrict__ Q, const float* __restrict__ K,
    const float* __restrict__ V, const unsigned char* __restrict__ pad,
    float* __restrict__ O)
{
    const int qt = blockIdx.x;
    const int bh = blockIdx.y;
    const int b  = bh >> 4;
    const int h  = bh & 15;

    extern __shared__ uint32_t sm[];
    uint32_t* Qh = sm;                    // [64][SQ] (q, d) tf32 hi
    uint32_t* Ql = Qh + 64 * SQ;
    uint32_t* Kh = Ql + 64 * SQ;          // [64][SQ] (k, d) hi; reused as P hi
    uint32_t* Kl = Kh + 64 * SQ;
    uint32_t* Vh = Kl + 64 * SQ;          // [64][SV] (k, d) hi
    uint32_t* Vl = Vh + 64 * SV;

    __shared__ float red[64][2];
    __shared__ float m_s[64], l_s[64], sc_s[64], pads[64];

    const int tid  = threadIdx.x;
    const int warp = tid >> 5;
    const int lane = tid & 31;
    const int r    = lane >> 2;    // 0..7
    const int c    = lane & 3;     // 0..3
    const int wq   = warp >> 1;    // 0..3
    const int wk   = warp & 1;     // 0..1

    const float slope = exp2f(-0.5f * (float)(h + 1));

    const float* Qb = Q + ((size_t)b * SEQ_L) * D_MODEL + h * HEAD_DIM;
    const float* Kb = K + ((size_t)b * SEQ_L) * D_MODEL + h * HEAD_DIM;
    const float* Vb = V + ((size_t)b * SEQ_L) * D_MODEL + h * HEAD_DIM;
    const unsigned char* padb = pad + (size_t)b * SEQ_L;

    // Load Q tile (scaled by 1/sqrt(d)=0.125), split tf32 hi/lo
    for (int t = tid; t < 64 * 16; t += 256) {
        const int row = t >> 4, seg = (t & 15) * 4;
        float4 qv = *(const float4*)(Qb + (size_t)(qt * 64 + row) * D_MODEL + seg);
        uint4 hi, lo;
        split_tf32(qv.x * 0.125f, hi.x, lo.x);
        split_tf32(qv.y * 0.125f, hi.y, lo.y);
        split_tf32(qv.z * 0.125f, hi.z, lo.z);
        split_tf32(qv.w * 0.125f, hi.w, lo.w);
        *(uint4*)(Qh + row * SQ + seg) = hi;
        *(uint4*)(Ql + row * SQ + seg) = lo;
    }
    if (tid < 64) { m_s[tid] = -1e30f; l_s[tid] = 0.f; }

    float Oacc[4][4];
#pragma unroll
    for (int nt = 0; nt < 4; ++nt)
#pragma unroll
        for (int q = 0; q < 4; ++q) Oacc[nt][q] = 0.f;

    const int row0 = 16 * wq + r;        // local query rows: row0, row0+8
    const int kt_lo = (qt >= 8) ? (qt - 8) : 0;

    for (int kt = kt_lo; kt <= qt; ++kt) {
        __syncthreads();   // previous tile fully consumed (P/V reads done)
        for (int t = tid; t < 64 * 16; t += 256) {
            const int row = t >> 4, seg = (t & 15) * 4;
            float4 kv = *(const float4*)(Kb + (size_t)(kt * 64 + row) * D_MODEL + seg);
            float4 vv = *(const float4*)(Vb + (size_t)(kt * 64 + row) * D_MODEL + seg);
            uint4 khi, klo, vhi, vlo;
            split_tf32(kv.x, khi.x, klo.x); split_tf32(kv.y, khi.y, klo.y);
            split_tf32(kv.z, khi.z, klo.z); split_tf32(kv.w, khi.w, klo.w);
            split_tf32(vv.x, vhi.x, vlo.x); split_tf32(vv.y, vhi.y, vlo.y);
            split_tf32(vv.z, vhi.z, vlo.z); split_tf32(vv.w, vhi.w, vlo.w);
            *(uint4*)(Kh + row * SQ + seg) = khi;
            *(uint4*)(Kl + row * SQ + seg) = klo;
            *(uint4*)(Vh + row * SV + seg) = vhi;
            *(uint4*)(Vl + row * SV + seg) = vlo;
        }
        if (tid < 64) pads[tid] = padb[kt * 64 + tid] ? -1e30f : 0.f;
        __syncthreads();

        // ---- S = Q . K^T  (warp tile 16 x 32, tf32x2 => 3 mma) ----
        float Sacc[4][4];
#pragma unroll
        for (int nt = 0; nt < 4; ++nt)
#pragma unroll
            for (int q = 0; q < 4; ++q) Sacc[nt][q] = 0.f;

#pragma unroll
        for (int ks = 0; ks < 8; ++ks) {
            const int abase = row0 * SQ + c + 8 * ks;
            uint32_t ah[4], al[4];
            ah[0] = Qh[abase];            ah[1] = Qh[abase + 8 * SQ];
            ah[2] = Qh[abase + 4];        ah[3] = Qh[abase + 8 * SQ + 4];
            al[0] = Ql[abase];            al[1] = Ql[abase + 8 * SQ];
            al[2] = Ql[abase + 4];        al[3] = Ql[abase + 8 * SQ + 4];
#pragma unroll
            for (int nt = 0; nt < 4; ++nt) {
                const int bbase = (32 * wk + 8 * nt + r) * SQ + c + 8 * ks;
                const uint32_t bh0 = Kh[bbase], bh1 = Kh[bbase + 4];
                const uint32_t bl0 = Kl[bbase], bl1 = Kl[bbase + 4];
                mma_tf32(Sacc[nt], ah, bh0, bh1);
                mma_tf32(Sacc[nt], ah, bl0, bl1);
                mma_tf32(Sacc[nt], al, bh0, bh1);
            }
        }

        // ---- mask + ALiBi + row max ----
        const int gi0 = qt * 64 + row0;
        const int gi1 = gi0 + 8;
        float mx0 = -1e30f, mx1 = -1e30f;
#pragma unroll
        for (int nt = 0; nt < 4; ++nt) {
            const int jl = 32 * wk + 8 * nt + 2 * c;
            const int gj0 = kt * 64 + jl, gj1 = gj0 + 1;
            const float pd0 = pads[jl], pd1 = pads[jl + 1];
            float s;
            s = Sacc[nt][0] + slope * (float)(gj0 - gi0) + pd0;
            if (gj0 > gi0 || gj0 < gi0 - WINDOW) s = -1e30f;
            Sacc[nt][0] = s; mx0 = fmaxf(mx0, s);
            s = Sacc[nt][1] + slope * (float)(gj1 - gi0) + pd1;
            if (gj1 > gi0 || gj1 < gi0 - WINDOW) s = -1e30f;
            Sacc[nt][1] = s; mx0 = fmaxf(mx0, s);
            s = Sacc[nt][2] + slope * (float)(gj0 - gi1) + pd0;
            if (gj0 > gi1 || gj0 < gi1 - WINDOW) s = -1e30f;
            Sacc[nt][2] = s; mx1 = fmaxf(mx1, s);
            s = Sacc[nt][3] + slope * (float)(gj1 - gi1) + pd1;
            if (gj1 > gi1 || gj1 < gi1 - WINDOW) s = -1e30f;
            Sacc[nt][3] = s; mx1 = fmaxf(mx1, s);
        }
        mx0 = fmaxf(mx0, __shfl_xor_sync(0xffffffffu, mx0, 1));
        mx0 = fmaxf(mx0, __shfl_xor_sync(0xffffffffu, mx0, 2));
        mx1 = fmaxf(mx1, __shfl_xor_sync(0xffffffffu, mx1, 1));
        mx1 = fmaxf(mx1, __shfl_xor_sync(0xffffffffu, mx1, 2));
        if (c == 0) { red[row0][wk] = mx0; red[row0 + 8][wk] = mx1; }
        __syncthreads();

        if (tid < 64) {
            const float mt = fmaxf(red[tid][0], red[tid][1]);
            const float mo = m_s[tid];
            const float mn = fmaxf(mo, mt);
            const float sc = __expf(mo - mn);
            m_s[tid] = mn; sc_s[tid] = sc; l_s[tid] *= sc;
        }
        __syncthreads();

        // ---- P = exp(S-m), write tf32x2 P into K buffers; rescale O ----
        const float mn0 = m_s[row0], mn1 = m_s[row0 + 8];
        const float sc0 = sc_s[row0], sc1 = sc_s[row0 + 8];
        float rs0 = 0.f, rs1 = 0.f;
#pragma unroll
        for (int nt = 0; nt < 4; ++nt) {
            const int jl = 32 * wk + 8 * nt + 2 * c;
            float p0 = (Sacc[nt][0] < -1e29f) ? 0.f : __expf(Sacc[nt][0] - mn0);
            float p1 = (Sacc[nt][1] < -1e29f) ? 0.f : __expf(Sacc[nt][1] - mn0);
            float p2 = (Sacc[nt][2] < -1e29f) ? 0.f : __expf(Sacc[nt][2] - mn1);
            float p3 = (Sacc[nt][3] < -1e29f) ? 0.f : __expf(Sacc[nt][3] - mn1);
            rs0 += p0 + p1; rs1 += p2 + p3;
            uint2 hi, lo;
            split_tf32(p0, hi.x, lo.x); split_tf32(p1, hi.y, lo.y);
            *(uint2*)(Kh + row0 * SQ + jl) = hi;
            *(uint2*)(Kl + row0 * SQ + jl) = lo;
            split_tf32(p2, hi.x, lo.x); split_tf32(p3, hi.y, lo.y);
            *(uint2*)(Kh + (row0 + 8) * SQ + jl) = hi;
            *(uint2*)(Kl + (row0 + 8) * SQ + jl) = lo;
            Oacc[nt][0] *= sc0; Oacc[nt][1] *= sc0;
            Oacc[nt][2] *= sc1; Oacc[nt][3] *= sc1;
        }
        rs0 += __shfl_xor_sync(0xffffffffu, rs0, 1);
        rs0 += __shfl_xor_sync(0xffffffffu, rs0, 2);
        rs1 += __shfl_xor_sync(0xffffffffu, rs1, 1);
        rs1 += __shfl_xor_sync(0xffffffffu, rs1, 2);
        if (c == 0) { red[row0][wk] = rs0; red[row0 + 8][wk] = rs1; }
        __syncthreads();

        if (tid < 64) l_s[tid] += red[tid][0] + red[tid][1];

        // ---- O += P . V  (warp tile 16 x 32 d-cols, tf32x2) ----
#pragma unroll
        for (int ks = 0; ks < 8; ++ks) {
            const int abase = row0 * SQ + c + 8 * ks;
            uint32_t ah[4], al[4];
            ah[0] = Kh[abase];            ah[1] = Kh[abase + 8 * SQ];
            ah[2] = Kh[abase + 4];        ah[3] = Kh[abase + 8 * SQ + 4];
            al[0] = Kl[abase];            al[1] = Kl[abase + 8 * SQ];
            al[2] = Kl[abase + 4];        al[3] = Kl[abase + 8 * SQ + 4];
#pragma unroll
            for (int nt = 0; nt < 4; ++nt) {
                const int bbase = (c + 8 * ks) * SV + 32 * wk + 8 * nt + r;
                const uint32_t bh0 = Vh[bbase], bh1 = Vh[bbase + 4 * SV];
                const uint32_t bl0 = Vl[bbase], bl1 = Vl[bbase + 4 * SV];
                mma_tf32(Oacc[nt], ah, bh0, bh1);
                mma_tf32(Oacc[nt], ah, bl0, bl1);
                mma_tf32(Oacc[nt], al, bh0, bh1);
            }
        }
    }
    __syncthreads();   // l_s final

    const float inv0 = 1.f / l_s[row0];
    const float inv1 = 1.f / l_s[row0 + 8];
    const int gi0 = qt * 64 + row0;
    float* Ob = O + ((size_t)b * SEQ_L + gi0) * D_MODEL + h * HEAD_DIM;
#pragma unroll
    for (int nt = 0; nt < 4; ++nt) {
        const int dcol = 32 * wk + 8 * nt + 2 * c;
        *(float2*)(Ob + dcol) =
            make_float2(Oacc[nt][0] * inv0, Oacc[nt][1] * inv0);
        *(float2*)(Ob + 8 * D_MODEL + dcol) =
            make_float2(Oacc[nt][2] * inv1, Oacc[nt][3] * inv1);
    }
}

// ---------------------------------------------------------------------------
extern "C" void kernel_launch(void* const* d_in, const int* in_sizes, int n_in,
                              void* d_out, int out_size)
{
    const float* x  = (const float*)d_in[0];
    const unsigned char* pad = (const unsigned char*)d_in[1];
    const float* Wq = (const float*)d_in[2];
    const float* bq = (const float*)d_in[3];
    const float* Wk = (const float*)d_in[4];
    const float* bk = (const float*)d_in[5];
    const float* Wv = (const float*)d_in[6];
    const float* bv = (const float*)d_in[7];
    const float* Wo = (const float*)d_in[8];
    const float* bo = (const float*)d_in[9];
    float* out = (float*)d_out;

    float *q, *k, *v, *att;
    cudaGetSymbolAddress((void**)&q,   g_q);
    cudaGetSymbolAddress((void**)&k,   g_k);
    cudaGetSymbolAddress((void**)&v,   g_v);
    cudaGetSymbolAddress((void**)&att, g_att);

    cudaFuncSetAttribute(attn_alibi_mma,
                         cudaFuncAttributeMaxDynamicSharedMemorySize,
                         ATTN_SMEM_BYTES);

    const int M = BATCH * SEQ_L;           // 8192
    dim3 ggrid(D_MODEL / 128, M / 128);    // (8, 64)
    gemm_tf32_nt_bias<<<ggrid, 256>>>(x, Wq, bq, q, M, D_MODEL, D_MODEL);
    gemm_tf32_nt_bias<<<ggrid, 256>>>(x, Wk, bk, k, M, D_MODEL, D_MODEL);
    gemm_tf32_nt_bias<<<ggrid, 256>>>(x, Wv, bv, v, M, D_MODEL, D_MODEL);

    dim3 agrid(SEQ_L / 64, BATCH * N_HEADS);   // (32, 64)
    attn_alibi_mma<<<agrid, 256, ATTN_SMEM_BYTES>>>(q, k, v, pad, att);

    gemm_tf32_nt_bias<<<ggrid, 256>>>(att, Wo, bo, out, M, D_MODEL, D_MODEL);
}

// round 4
// speedup vs baseline: 1.9912x; 1.1072x over previous
#include <cuda_runtime.h>
#include <cstdint>

#define D_MODEL  1024
#define N_HEADS  16
#define HEAD_DIM 64
#define SEQ_L    2048
#define BATCH    4
#define WINDOW   512

__device__ float g_q[BATCH * SEQ_L * D_MODEL];
__device__ float g_k[BATCH * SEQ_L * D_MODEL];
__device__ float g_v[BATCH * SEQ_L * D_MODEL];
__device__ float g_att[BATCH * SEQ_L * D_MODEL];

__device__ __forceinline__ uint32_t f2tf32(float f) {
    uint32_t u;
    asm("cvt.rna.tf32.f32 %0, %1;" : "=r"(u) : "f"(f));
    return u;
}
__device__ __forceinline__ void split_tf32(float x, uint32_t& hi, uint32_t& lo) {
    hi = f2tf32(x);
    lo = f2tf32(x - __uint_as_float(hi));
}
__device__ __forceinline__ void mma_tf32(float* d, const uint32_t* a,
                                         uint32_t b0, uint32_t b1) {
    asm volatile(
        "mma.sync.aligned.m16n8k8.row.col.f32.tf32.tf32.f32 "
        "{%0,%1,%2,%3}, {%4,%5,%6,%7}, {%8,%9}, {%0,%1,%2,%3};"
        : "+f"(d[0]), "+f"(d[1]), "+f"(d[2]), "+f"(d[3])
        : "r"(a[0]), "r"(a[1]), "r"(a[2]), "r"(a[3]), "r"(b0), "r"(b1));
}

// ---------------------------------------------------------------------------
// tf32 GEMM, double-buffered smem, one barrier per 32-K iteration.
// C[m][n] = sum_k A[m][k]*W[n][k] + bias[n].  blockIdx.z selects (W,b,C).
// Block tile 128x128, 256 threads = 8 warps (2Mx4N), warp tile 64x32.
// ---------------------------------------------------------------------------
__global__ __launch_bounds__(256, 2) void gemm_tf32_db(
    const float* __restrict__ A,
    const float* __restrict__ W0, const float* __restrict__ W1,
    const float* __restrict__ W2,
    const float* __restrict__ b0, const float* __restrict__ b1,
    const float* __restrict__ b2,
    float* __restrict__ C0, float* __restrict__ C1, float* __restrict__ C2,
    int M, int N, int K)
{
    __shared__ uint32_t As[2][128 * 32];
    __shared__ uint32_t Bs[2][128 * 32];

    const int z = blockIdx.z;
    const float* W    = (z == 0) ? W0 : (z == 1) ? W1 : W2;
    const float* bias = (z == 0) ? b0 : (z == 1) ? b1 : b2;
    float*       C    = (z == 0) ? C0 : (z == 1) ? C1 : C2;

    const int tid    = threadIdx.x;
    const int warpId = tid >> 5;
    const int lane   = tid & 31;
    const int r      = lane >> 2;
    const int c      = lane & 3;
    const int warpM  = (warpId >> 2) * 64;
    const int warpN  = (warpId & 3) * 32;
    const int m0     = blockIdx.y * 128;
    const int n0     = blockIdx.x * 128;

    const int gRow = tid >> 1;
    const int gK   = (tid & 1) * 16;
    const float* Ag = A + (size_t)(m0 + gRow) * K + gK;
    const float* Wg = W + (size_t)(n0 + gRow) * K + gK;
    const int swr   = (gRow & 7) << 2;
    const int rsw   = r << 2;

    float acc[4][4][4];
#pragma unroll
    for (int mt = 0; mt < 4; ++mt)
#pragma unroll
        for (int nt = 0; nt < 4; ++nt)
#pragma unroll
            for (int q = 0; q < 4; ++q) acc[mt][nt][q] = 0.f;

    float4 pa[4], pw[4];
#pragma unroll
    for (int i = 0; i < 4; ++i) {
        pa[i] = *(const float4*)(Ag + i * 4);
        pw[i] = *(const float4*)(Wg + i * 4);
    }
    // store stage 0
    {
        uint32_t* AsW = As[0] + gRow * 32;
        uint32_t* BsW = Bs[0] + gRow * 32;
#pragma unroll
        for (int i = 0; i < 4; ++i) {
            const int sc = (gK + i * 4) ^ swr;
            *(uint4*)(AsW + sc) = make_uint4(f2tf32(pa[i].x), f2tf32(pa[i].y),
                                             f2tf32(pa[i].z), f2tf32(pa[i].w));
            *(uint4*)(BsW + sc) = make_uint4(f2tf32(pw[i].x), f2tf32(pw[i].y),
                                             f2tf32(pw[i].z), f2tf32(pw[i].w));
        }
    }
    __syncthreads();

    int st = 0;
    for (int k0 = 0; k0 < K; k0 += 32) {
        const bool has_next = (k0 + 32) < K;
        if (has_next) {
#pragma unroll
            for (int i = 0; i < 4; ++i) {
                pa[i] = *(const float4*)(Ag + k0 + 32 + i * 4);
                pw[i] = *(const float4*)(Wg + k0 + 32 + i * 4);
            }
        }

        const uint32_t* Asr = As[st];
        const uint32_t* Bsr = Bs[st];
#pragma unroll
        for (int ks = 0; ks < 4; ++ks) {
            const int col0 = (8 * ks + c) ^ rsw;
            const int col1 = (8 * ks + c + 4) ^ rsw;

            uint32_t af[4][4];
#pragma unroll
            for (int mt = 0; mt < 4; ++mt) {
                const int base = (warpM + 16 * mt + r) * 32;
                af[mt][0] = Asr[base + col0];
                af[mt][1] = Asr[base + 256 + col0];
                af[mt][2] = Asr[base + col1];
                af[mt][3] = Asr[base + 256 + col1];
            }
#pragma unroll
            for (int nt = 0; nt < 4; ++nt) {
                const int nbase = (warpN + 8 * nt + r) * 32;
                const uint32_t bb0 = Bsr[nbase + col0];
                const uint32_t bb1 = Bsr[nbase + col1];
#pragma unroll
                for (int mt = 0; mt < 4; ++mt)
                    mma_tf32(acc[mt][nt], af[mt], bb0, bb1);
            }
        }

        if (has_next) {
            uint32_t* AsW = As[st ^ 1] + gRow * 32;
            uint32_t* BsW = Bs[st ^ 1] + gRow * 32;
#pragma unroll
            for (int i = 0; i < 4; ++i) {
                const int sc = (gK + i * 4) ^ swr;
                *(uint4*)(AsW + sc) = make_uint4(f2tf32(pa[i].x), f2tf32(pa[i].y),
                                                 f2tf32(pa[i].z), f2tf32(pa[i].w));
                *(uint4*)(BsW + sc) = make_uint4(f2tf32(pw[i].x), f2tf32(pw[i].y),
                                                 f2tf32(pw[i].z), f2tf32(pw[i].w));
            }
            __syncthreads();
        }
        st ^= 1;
    }

#pragma unroll
    for (int nt = 0; nt < 4; ++nt) {
        const int col = n0 + warpN + 8 * nt + 2 * c;
        const float2 bv = *(const float2*)&bias[col];
#pragma unroll
        for (int mt = 0; mt < 4; ++mt) {
            const int row = m0 + warpM + 16 * mt + r;
            float2 o0 = make_float2(acc[mt][nt][0] + bv.x, acc[mt][nt][1] + bv.y);
            float2 o1 = make_float2(acc[mt][nt][2] + bv.x, acc[mt][nt][3] + bv.y);
            *(float2*)&C[(size_t)row * N + col]       = o0;
            *(float2*)&C[(size_t)(row + 8) * N + col] = o1;
        }
    }
}

// ---------------------------------------------------------------------------
// Flash attention, tensor-core tf32x2 (unchanged from round 3)
// ---------------------------------------------------------------------------
#define SQ 68
#define SV 72
#define ATTN_WORDS (4 * 64 * SQ + 2 * 64 * SV)
#define ATTN_SMEM_BYTES (ATTN_WORDS * 4)

__global__ __launch_bounds__(256) void attn_alibi_mma(
    const float* __restrict__ Q, const float* __restrict__ K,
    const float* __restrict__ V, const unsigned char* __restrict__ pad,
    float* __restrict__ O)
{
    const int qt = blockIdx.x;
    const int bh = blockIdx.y;
    const int b  = bh >> 4;
    const int h  = bh & 15;

    extern __shared__ uint32_t sm[];
    uint32_t* Qh = sm;
    uint32_t* Ql = Qh + 64 * SQ;
    uint32_t* Kh = Ql + 64 * SQ;
    uint32_t* Kl = Kh + 64 * SQ;
    uint32_t* Vh = Kl + 64 * SQ;
    uint32_t* Vl = Vh + 64 * SV;

    __shared__ float red[64][2];
    __shared__ float m_s[64], l_s[64], sc_s[64], pads[64];

    const int tid  = threadIdx.x;
    const int warp = tid >> 5;
    const int lane = tid & 31;
    const int r    = lane >> 2;
    const int c    = lane & 3;
    const int wq   = warp >> 1;
    const int wk   = warp & 1;

    const float slope = exp2f(-0.5f * (float)(h + 1));

    const float* Qb = Q + ((size_t)b * SEQ_L) * D_MODEL + h * HEAD_DIM;
    const float* Kb = K + ((size_t)b * SEQ_L) * D_MODEL + h * HEAD_DIM;
    const float* Vb = V + ((size_t)b * SEQ_L) * D_MODEL + h * HEAD_DIM;
    const unsigned char* padb = pad + (size_t)b * SEQ_L;

    for (int t = tid; t < 64 * 16; t += 256) {
        const int row = t >> 4, seg = (t & 15) * 4;
        float4 qv = *(const float4*)(Qb + (size_t)(qt * 64 + row) * D_MODEL + seg);
        uint4 hi, lo;
        split_tf32(qv.x * 0.125f, hi.x, lo.x);
        split_tf32(qv.y * 0.125f, hi.y, lo.y);
        split_tf32(qv.z * 0.125f, hi.z, lo.z);
        split_tf32(qv.w * 0.125f, hi.w, lo.w);
        *(uint4*)(Qh + row * SQ + seg) = hi;
        *(uint4*)(Ql + row * SQ + seg) = lo;
    }
    if (tid < 64) { m_s[tid] = -1e30f; l_s[tid] = 0.f; }

    float Oacc[4][4];
#pragma unroll
    for (int nt = 0; nt < 4; ++nt)
#pragma unroll
        for (int q = 0; q < 4; ++q) Oacc[nt][q] = 0.f;

    const int row0 = 16 * wq + r;
    const int kt_lo = (qt >= 8) ? (qt - 8) : 0;

    for (int kt = kt_lo; kt <= qt; ++kt) {
        __syncthreads();
        for (int t = tid; t < 64 * 16; t += 256) {
            const int row = t >> 4, seg = (t & 15) * 4;
            float4 kv = *(const float4*)(Kb + (size_t)(kt * 64 + row) * D_MODEL + seg);
            float4 vv = *(const float4*)(Vb + (size_t)(kt * 64 + row) * D_MODEL + seg);
            uint4 khi, klo, vhi, vlo;
            split_tf32(kv.x, khi.x, klo.x); split_tf32(kv.y, khi.y, klo.y);
            split_tf32(kv.z, khi.z, klo.z); split_tf32(kv.w, khi.w, klo.w);
            split_tf32(vv.x, vhi.x, vlo.x); split_tf32(vv.y, vhi.y, vlo.y);
            split_tf32(vv.z, vhi.z, vlo.z); split_tf32(vv.w, vhi.w, vlo.w);
            *(uint4*)(Kh + row * SQ + seg) = khi;
            *(uint4*)(Kl + row * SQ + seg) = klo;
            *(uint4*)(Vh + row * SV + seg) = vhi;
            *(uint4*)(Vl + row * SV + seg) = vlo;
        }
        if (tid < 64) pads[tid] = padb[kt * 64 + tid] ? -1e30f : 0.f;
        __syncthreads();

        float Sacc[4][4];
#pragma unroll
        for (int nt = 0; nt < 4; ++nt)
#pragma unroll
            for (int q = 0; q < 4; ++q) Sacc[nt][q] = 0.f;

#pragma unroll
        for (int ks = 0; ks < 8; ++ks) {
            const int abase = row0 * SQ + c + 8 * ks;
            uint32_t ah[4], al[4];
            ah[0] = Qh[abase];            ah[1] = Qh[abase + 8 * SQ];
            ah[2] = Qh[abase + 4];        ah[3] = Qh[abase + 8 * SQ + 4];
            al[0] = Ql[abase];            al[1] = Ql[abase + 8 * SQ];
            al[2] = Ql[abase + 4];        al[3] = Ql[abase + 8 * SQ + 4];
#pragma unroll
            for (int nt = 0; nt < 4; ++nt) {
                const int bbase = (32 * wk + 8 * nt + r) * SQ + c + 8 * ks;
                const uint32_t bh0 = Kh[bbase], bh1 = Kh[bbase + 4];
                const uint32_t bl0 = Kl[bbase], bl1 = Kl[bbase + 4];
                mma_tf32(Sacc[nt], ah, bh0, bh1);
                mma_tf32(Sacc[nt], ah, bl0, bl1);
                mma_tf32(Sacc[nt], al, bh0, bh1);
            }
        }

        const int gi0 = qt * 64 + row0;
        const int gi1 = gi0 + 8;
        float mx0 = -1e30f, mx1 = -1e30f;
#pragma unroll
        for (int nt = 0; nt < 4; ++nt) {
            const int jl = 32 * wk + 8 * nt + 2 * c;
            const int gj0 = kt * 64 + jl, gj1 = gj0 + 1;
            const float pd0 = pads[jl], pd1 = pads[jl + 1];
            float s;
            s = Sacc[nt][0] + slope * (float)(gj0 - gi0) + pd0;
            if (gj0 > gi0 || gj0 < gi0 - WINDOW) s = -1e30f;
            Sacc[nt][0] = s; mx0 = fmaxf(mx0, s);
            s = Sacc[nt][1] + slope * (float)(gj1 - gi0) + pd1;
            if (gj1 > gi0 || gj1 < gi0 - WINDOW) s = -1e30f;
            Sacc[nt][1] = s; mx0 = fmaxf(mx0, s);
            s = Sacc[nt][2] + slope * (float)(gj0 - gi1) + pd0;
            if (gj0 > gi1 || gj0 < gi1 - WINDOW) s = -1e30f;
            Sacc[nt][2] = s; mx1 = fmaxf(mx1, s);
            s = Sacc[nt][3] + slope * (float)(gj1 - gi1) + pd1;
            if (gj1 > gi1 || gj1 < gi1 - WINDOW) s = -1e30f;
            Sacc[nt][3] = s; mx1 = fmaxf(mx1, s);
        }
        mx0 = fmaxf(mx0, __shfl_xor_sync(0xffffffffu, mx0, 1));
        mx0 = fmaxf(mx0, __shfl_xor_sync(0xffffffffu, mx0, 2));
        mx1 = fmaxf(mx1, __shfl_xor_sync(0xffffffffu, mx1, 1));
        mx1 = fmaxf(mx1, __shfl_xor_sync(0xffffffffu, mx1, 2));
        if (c == 0) { red[row0][wk] = mx0; red[row0 + 8][wk] = mx1; }
        __syncthreads();

        if (tid < 64) {
            const float mt = fmaxf(red[tid][0], red[tid][1]);
            const float mo = m_s[tid];
            const float mn = fmaxf(mo, mt);
            const float sc = __expf(mo - mn);
            m_s[tid] = mn; sc_s[tid] = sc; l_s[tid] *= sc;
        }
        __syncthreads();

        const float mn0 = m_s[row0], mn1 = m_s[row0 + 8];
        const float sc0 = sc_s[row0], sc1 = sc_s[row0 + 8];
        float rs0 = 0.f, rs1 = 0.f;
#pragma unroll
        for (int nt = 0; nt < 4; ++nt) {
            const int jl = 32 * wk + 8 * nt + 2 * c;
            float p0 = (Sacc[nt][0] < -1e29f) ? 0.f : __expf(Sacc[nt][0] - mn0);
            float p1 = (Sacc[nt][1] < -1e29f) ? 0.f : __expf(Sacc[nt][1] - mn0);
            float p2 = (Sacc[nt][2] < -1e29f) ? 0.f : __expf(Sacc[nt][2] - mn1);
            float p3 = (Sacc[nt][3] < -1e29f) ? 0.f : __expf(Sacc[nt][3] - mn1);
            rs0 += p0 + p1; rs1 += p2 + p3;
            uint2 hi, lo;
            split_tf32(p0, hi.x, lo.x); split_tf32(p1, hi.y, lo.y);
            *(uint2*)(Kh + row0 * SQ + jl) = hi;
            *(uint2*)(Kl + row0 * SQ + jl) = lo;
            split_tf32(p2, hi.x, lo.x); split_tf32(p3, hi.y, lo.y);
            *(uint2*)(Kh + (row0 + 8) * SQ + jl) = hi;
            *(uint2*)(Kl + (row0 + 8) * SQ + jl) = lo;
            Oacc[nt][0] *= sc0; Oacc[nt][1] *= sc0;
            Oacc[nt][2] *= sc1; Oacc[nt][3] *= sc1;
        }
        rs0 += __shfl_xor_sync(0xffffffffu, rs0, 1);
        rs0 += __shfl_xor_sync(0xffffffffu, rs0, 2);
        rs1 += __shfl_xor_sync(0xffffffffu, rs1, 1);
        rs1 += __shfl_xor_sync(0xffffffffu, rs1, 2);
        if (c == 0) { red[row0][wk] = rs0; red[row0 + 8][wk] = rs1; }
        __syncthreads();

        if (tid < 64) l_s[tid] += red[tid][0] + red[tid][1];

#pragma unroll
        for (int ks = 0; ks < 8; ++ks) {
            const int abase = row0 * SQ + c + 8 * ks;
            uint32_t ah[4], al[4];
            ah[0] = Kh[abase];            ah[1] = Kh[abase + 8 * SQ];
            ah[2] = Kh[abase + 4];        ah[3] = Kh[abase + 8 * SQ + 4];
            al[0] = Kl[abase];            al[1] = Kl[abase + 8 * SQ];
            al[2] = Kl[abase + 4];        al[3] = Kl[abase + 8 * SQ + 4];
#pragma unroll
            for (int nt = 0; nt < 4; ++nt) {
                const int bbase = (c + 8 * ks) * SV + 32 * wk + 8 * nt + r;
                const uint32_t bh0 = Vh[bbase], bh1 = Vh[bbase + 4 * SV];
                const uint32_t bl0 = Vl[bbase], bl1 = Vl[bbase + 4 * SV];
                mma_tf32(Oacc[nt], ah, bh0, bh1);
                mma_tf32(Oacc[nt], ah, bl0, bl1);
                mma_tf32(Oacc[nt], al, bh0, bh1);
            }
        }
    }
    __syncthreads();

    const float inv0 = 1.f / l_s[row0];
    const float inv1 = 1.f / l_s[row0 + 8];
    const int gi0 = qt * 64 + row0;
    float* Ob = O + ((size_t)b * SEQ_L + gi0) * D_MODEL + h * HEAD_DIM;
#pragma unroll
    for (int nt = 0; nt < 4; ++nt) {
        const int dcol = 32 * wk + 8 * nt + 2 * c;
        *(float2*)(Ob + dcol) =
            make_float2(Oacc[nt][0] * inv0, Oacc[nt][1] * inv0);
        *(float2*)(Ob + 8 * D_MODEL + dcol) =
            make_float2(Oacc[nt][2] * inv1, Oacc[nt][3] * inv1);
    }
}

// ---------------------------------------------------------------------------
extern "C" void kernel_launch(void* const* d_in, const int* in_sizes, int n_in,
                              void* d_out, int out_size)
{
    const float* x  = (const float*)d_in[0];
    const unsigned char* pad = (const unsigned char*)d_in[1];
    const float* Wq = (const float*)d_in[2];
    const float* bq = (const float*)d_in[3];
    const float* Wk = (const float*)d_in[4];
    const float* bk = (const float*)d_in[5];
    const float* Wv = (const float*)d_in[6];
    const float* bv = (const float*)d_in[7];
    const float* Wo = (const float*)d_in[8];
    const float* bo = (const float*)d_in[9];
    float* out = (float*)d_out;

    float *q, *k, *v, *att;
    cudaGetSymbolAddress((void**)&q,   g_q);
    cudaGetSymbolAddress((void**)&k,   g_k);
    cudaGetSymbolAddress((void**)&v,   g_v);
    cudaGetSymbolAddress((void**)&att, g_att);

    cudaFuncSetAttribute(attn_alibi_mma,
                         cudaFuncAttributeMaxDynamicSharedMemorySize,
                         ATTN_SMEM_BYTES);

    const int M = BATCH * SEQ_L;              // 8192
    dim3 qkv_grid(D_MODEL / 128, M / 128, 3); // (8, 64, 3)
    gemm_tf32_db<<<qkv_grid, 256>>>(x, Wq, Wk, Wv, bq, bk, bv,
                                    q, k, v, M, D_MODEL, D_MODEL);

    dim3 agrid(SEQ_L / 64, BATCH * N_HEADS);  // (32, 64)
    attn_alibi_mma<<<agrid, 256, ATTN_SMEM_BYTES>>>(q, k, v, pad, att);

    dim3 o_grid(D_MODEL / 128, M / 128, 1);
    gemm_tf32_db<<<o_grid, 256>>>(att, Wo, Wo, Wo, bo, bo, bo,
                                  out, out, out, M, D_MODEL, D_MODEL);
}

// round 7
// speedup vs baseline: 2.3420x; 1.1762x over previous
#include <cuda_runtime.h>
#include <cstdint>

#define D_MODEL  1024
#define N_HEADS  16
#define HEAD_DIM 64
#define SEQ_L    2048
#define BATCH    4
#define WINDOW   512

__device__ float g_q[BATCH * SEQ_L * D_MODEL];
__device__ float g_k[BATCH * SEQ_L * D_MODEL];
__device__ float g_v[BATCH * SEQ_L * D_MODEL];
__device__ float g_att[BATCH * SEQ_L * D_MODEL];

__device__ __forceinline__ uint32_t f2tf32(float f) {
    uint32_t u;
    asm("cvt.rna.tf32.f32 %0, %1;" : "=r"(u) : "f"(f));
    return u;
}
__device__ __forceinline__ void split_tf32(float x, uint32_t& hi, uint32_t& lo) {
    hi = f2tf32(x);
    lo = f2tf32(x - __uint_as_float(hi));
}
__device__ __forceinline__ void mma_tf32(float* d, const uint32_t* a,
                                         uint32_t b0, uint32_t b1) {
    asm volatile(
        "mma.sync.aligned.m16n8k8.row.col.f32.tf32.tf32.f32 "
        "{%0,%1,%2,%3}, {%4,%5,%6,%7}, {%8,%9}, {%0,%1,%2,%3};"
        : "+f"(d[0]), "+f"(d[1]), "+f"(d[2]), "+f"(d[3])
        : "r"(a[0]), "r"(a[1]), "r"(a[2]), "r"(a[3]), "r"(b0), "r"(b1));
}
__device__ __forceinline__ uint32_t smem_u32(const void* p) {
    uint32_t a;
    asm("{ .reg .u64 t; cvta.to.shared.u64 t, %1; cvt.u32.u64 %0, t; }"
        : "=r"(a) : "l"(p));
    return a;
}
__device__ __forceinline__ void ldsm_x4(uint32_t addr, uint32_t* r) {
    asm volatile(
        "ldmatrix.sync.aligned.m8n8.x4.shared.b16 {%0,%1,%2,%3}, [%4];"
        : "=r"(r[0]), "=r"(r[1]), "=r"(r[2]), "=r"(r[3]) : "r"(addr));
}

// ---------------------------------------------------------------------------
// tf32 GEMM (mma.sync), double-buffered smem, ldmatrix fragment loads.
// C[m][n] = sum_k A[m][k]*W[n][k] + bias[n].  blockIdx.z selects (W,b,C).
// Block tile 128x128, 256 threads = 8 warps (2Mx4N), warp tile 64x32.
// smem: [row][32 k-words], 16B-chunk XOR swizzle: chunk' = chunk ^ (row&7).
// ---------------------------------------------------------------------------
__global__ __launch_bounds__(256, 2) void gemm_tf32_db(
    const float* __restrict__ A,
    const float* __restrict__ W0, const float* __restrict__ W1,
    const float* __restrict__ W2,
    const float* __restrict__ b0, const float* __restrict__ b1,
    const float* __restrict__ b2,
    float* __restrict__ C0, float* __restrict__ C1, float* __restrict__ C2,
    int M, int N, int K)
{
    __shared__ uint32_t As[2][128 * 32];
    __shared__ uint32_t Bs[2][128 * 32];

    const int z = blockIdx.z;
    const float* W    = (z == 0) ? W0 : (z == 1) ? W1 : W2;
    const float* bias = (z == 0) ? b0 : (z == 1) ? b1 : b2;
    float*       C    = (z == 0) ? C0 : (z == 1) ? C1 : C2;

    const int tid    = threadIdx.x;
    const int warpId = tid >> 5;
    const int lane   = tid & 31;
    const int r      = lane >> 2;
    const int c      = lane & 3;
    const int warpM  = (warpId >> 2) * 64;
    const int warpN  = (warpId & 3) * 32;
    const int m0     = blockIdx.y * 128;
    const int n0     = blockIdx.x * 128;

    const int gRow = tid >> 1;
    const int gK   = (tid & 1) * 16;
    const float* Ag = A + (size_t)(m0 + gRow) * K + gK;
    const float* Wg = W + (size_t)(n0 + gRow) * K + gK;
    const int swr   = (gRow & 7) << 2;   // word-level XOR = chunk ^ (row&7)

    // ldmatrix per-lane addressing
    const int lrow8 = lane & 7;
    const int tsel  = lane >> 3;                       // 0..3
    const int aRow  = warpM + ((tsel & 1) << 3) + lrow8;  // + 16*mt
    const int aCa   = tsel >> 1;                       // chunk add (k hi)
    const int bRow  = warpN + ((tsel >> 1) << 3) + lrow8; // + 16*p
    const int bCa   = tsel & 1;

    const uint32_t asb0 = smem_u32(As[0]), asb1 = smem_u32(As[1]);
    const uint32_t bsb0 = smem_u32(Bs[0]), bsb1 = smem_u32(Bs[1]);

    float acc[4][4][4];
#pragma unroll
    for (int mt = 0; mt < 4; ++mt)
#pragma unroll
        for (int nt = 0; nt < 4; ++nt)
#pragma unroll
            for (int q = 0; q < 4; ++q) acc[mt][nt][q] = 0.f;

    float4 pa[4], pw[4];
#pragma unroll
    for (int i = 0; i < 4; ++i) {
        pa[i] = *(const float4*)(Ag + i * 4);
        pw[i] = *(const float4*)(Wg + i * 4);
    }
    {
        uint32_t* AsW = As[0] + gRow * 32;
        uint32_t* BsW = Bs[0] + gRow * 32;
#pragma unroll
        for (int i = 0; i < 4; ++i) {
            const int sc = (gK + i * 4) ^ swr;
            *(uint4*)(AsW + sc) = make_uint4(f2tf32(pa[i].x), f2tf32(pa[i].y),
                                             f2tf32(pa[i].z), f2tf32(pa[i].w));
            *(uint4*)(BsW + sc) = make_uint4(f2tf32(pw[i].x), f2tf32(pw[i].y),
                                             f2tf32(pw[i].z), f2tf32(pw[i].w));
        }
    }
    __syncthreads();

    int st = 0;
    for (int k0 = 0; k0 < K; k0 += 32) {
        const bool has_next = (k0 + 32) < K;
        if (has_next) {
#pragma unroll
            for (int i = 0; i < 4; ++i) {
                pa[i] = *(const float4*)(Ag + k0 + 32 + i * 4);
                pw[i] = *(const float4*)(Wg + k0 + 32 + i * 4);
            }
        }

        const uint32_t asb = st ? asb1 : asb0;
        const uint32_t bsb = st ? bsb1 : bsb0;
#pragma unroll
        for (int ks = 0; ks < 4; ++ks) {
            uint32_t af[4][4];
            const uint32_t aChunk = (uint32_t)((2 * ks + aCa) ^ lrow8) << 4;
#pragma unroll
            for (int mt = 0; mt < 4; ++mt)
                ldsm_x4(asb + ((uint32_t)(aRow + 16 * mt) << 7) + aChunk, af[mt]);

            uint32_t bf[2][4];
            const uint32_t bChunk = (uint32_t)((2 * ks + bCa) ^ lrow8) << 4;
#pragma unroll
            for (int p = 0; p < 2; ++p)
                ldsm_x4(bsb + ((uint32_t)(bRow + 16 * p) << 7) + bChunk, bf[p]);

#pragma unroll
            for (int nt = 0; nt < 4; ++nt) {
                const uint32_t bb0 = bf[nt >> 1][(nt & 1) << 1];
                const uint32_t bb1 = bf[nt >> 1][((nt & 1) << 1) + 1];
#pragma unroll
                for (int mt = 0; mt < 4; ++mt)
                    mma_tf32(acc[mt][nt], af[mt], bb0, bb1);
            }
        }

        if (has_next) {
            uint32_t* AsW = As[st ^ 1] + gRow * 32;
            uint32_t* BsW = Bs[st ^ 1] + gRow * 32;
#pragma unroll
            for (int i = 0; i < 4; ++i) {
                const int sc = (gK + i * 4) ^ swr;
                *(uint4*)(AsW + sc) = make_uint4(f2tf32(pa[i].x), f2tf32(pa[i].y),
                                                 f2tf32(pa[i].z), f2tf32(pa[i].w));
                *(uint4*)(BsW + sc) = make_uint4(f2tf32(pw[i].x), f2tf32(pw[i].y),
                                                 f2tf32(pw[i].z), f2tf32(pw[i].w));
            }
            __syncthreads();
        }
        st ^= 1;
    }

#pragma unroll
    for (int nt = 0; nt < 4; ++nt) {
        const int col = n0 + warpN + 8 * nt + 2 * c;
        const float2 bv = *(const float2*)&bias[col];
#pragma unroll
        for (int mt = 0; mt < 4; ++mt) {
            const int row = m0 + warpM + 16 * mt + r;
            float2 o0 = make_float2(acc[mt][nt][0] + bv.x, acc[mt][nt][1] + bv.y);
            float2 o1 = make_float2(acc[mt][nt][2] + bv.x, acc[mt][nt][3] + bv.y);
            *(float2*)&C[(size_t)row * N + col]       = o0;
            *(float2*)&C[(size_t)(row + 8) * N + col] = o1;
        }
    }
}

// ---------------------------------------------------------------------------
// Flash attention, tf32x2 mma + ldmatrix for Q/K/P fragments.
// smem strides: Q/K/P at 68 words (stride 272B = 17*16B -> chunk index
// (17r + w4) % 8 = r + w4: the 8 ldmatrix rows hit distinct 16B banks).
// ---------------------------------------------------------------------------
#define SQ 68
#define SV 72
#define ATTN_WORDS (4 * 64 * SQ + 2 * 64 * SV)
#define ATTN_SMEM_BYTES (ATTN_WORDS * 4)

__global__ __launch_bounds__(256) void attn_alibi_mma(
    const float* __restrict__ Q, const float* __restrict__ K,
    const float* __restrict__ V, const unsigned char* __restrict__ pad,
    float* __restrict__ O)
{
    const int qt = blockIdx.x;
    const int bh = blockIdx.y;
    const int b  = bh >> 4;
    const int h  = bh & 15;

    extern __shared__ uint32_t sm[];
    uint32_t* Qh = sm;
    uint32_t* Ql = Qh + 64 * SQ;
    uint32_t* Kh = Ql + 64 * SQ;
    uint32_t* Kl = Kh + 64 * SQ;
    uint32_t* Vh = Kl + 64 * SQ;
    uint32_t* Vl = Vh + 64 * SV;

    __shared__ float red[64][2];
    __shared__ float m_s[64], l_s[64], sc_s[64], pads[64];

    const int tid  = threadIdx.x;
    const int warp = tid >> 5;
    const int lane = tid & 31;
    const int r    = lane >> 2;
    const int c    = lane & 3;
    const int wq   = warp >> 1;
    const int wk   = warp & 1;

    // ldmatrix per-lane addressing
    const int lrow8 = lane & 7;
    const int tsel  = lane >> 3;
    const int qaRow = 16 * wq + ((tsel & 1) << 3) + lrow8;  // A-frag rows
    const int qaW   = (tsel >> 1) << 2;                     // +0/+4 words
    const int kbRow = 32 * wk + ((tsel >> 1) << 3) + lrow8; // B-frag rows (+16*p)
    const int kbW   = (tsel & 1) << 2;

    const uint32_t qh_b = smem_u32(Qh) + (uint32_t)(qaRow * SQ + qaW) * 4;
    const uint32_t ql_b = smem_u32(Ql) + (uint32_t)(qaRow * SQ + qaW) * 4;
    const uint32_t kh_b = smem_u32(Kh) + (uint32_t)(kbRow * SQ + kbW) * 4;
    const uint32_t kl_b = smem_u32(Kl) + (uint32_t)(kbRow * SQ + kbW) * 4;
    const uint32_t ph_b = smem_u32(Kh) + (uint32_t)(qaRow * SQ + qaW) * 4;
    const uint32_t pl_b = smem_u32(Kl) + (uint32_t)(qaRow * SQ + qaW) * 4;
    const uint32_t ntp_step = (uint32_t)(16 * SQ) * 4;

    const float slope = exp2f(-0.5f * (float)(h + 1));

    const float* Qb = Q + ((size_t)b * SEQ_L) * D_MODEL + h * HEAD_DIM;
    const float* Kb = K + ((size_t)b * SEQ_L) * D_MODEL + h * HEAD_DIM;
    const float* Vb = V + ((size_t)b * SEQ_L) * D_MODEL + h * HEAD_DIM;
    const unsigned char* padb = pad + (size_t)b * SEQ_L;

    for (int t = tid; t < 64 * 16; t += 256) {
        const int row = t >> 4, seg = (t & 15) * 4;
        float4 qv = *(const float4*)(Qb + (size_t)(qt * 64 + row) * D_MODEL + seg);
        uint4 hi, lo;
        split_tf32(qv.x * 0.125f, hi.x, lo.x);
        split_tf32(qv.y * 0.125f, hi.y, lo.y);
        split_tf32(qv.z * 0.125f, hi.z, lo.z);
        split_tf32(qv.w * 0.125f, hi.w, lo.w);
        *(uint4*)(Qh + row * SQ + seg) = hi;
        *(uint4*)(Ql + row * SQ + seg) = lo;
    }
    if (tid < 64) { m_s[tid] = -1e30f; l_s[tid] = 0.f; }

    float Oacc[4][4];
#pragma unroll
    for (int nt = 0; nt < 4; ++nt)
#pragma unroll
        for (int q = 0; q < 4; ++q) Oacc[nt][q] = 0.f;

    const int row0 = 16 * wq + r;
    const int kt_lo = (qt >= 8) ? (qt - 8) : 0;

    for (int kt = kt_lo; kt <= qt; ++kt) {
        __syncthreads();
        for (int t = tid; t < 64 * 16; t += 256) {
            const int row = t >> 4, seg = (t & 15) * 4;
            float4 kv = *(const float4*)(Kb + (size_t)(kt * 64 + row) * D_MODEL + seg);
            float4 vv = *(const float4*)(Vb + (size_t)(kt * 64 + row) * D_MODEL + seg);
            uint4 khi, klo, vhi, vlo;
            split_tf32(kv.x, khi.x, klo.x); split_tf32(kv.y, khi.y, klo.y);
            split_tf32(kv.z, khi.z, klo.z); split_tf32(kv.w, khi.w, klo.w);
            split_tf32(vv.x, vhi.x, vlo.x); split_tf32(vv.y, vhi.y, vlo.y);
            split_tf32(vv.z, vhi.z, vlo.z); split_tf32(vv.w, vhi.w, vlo.w);
            *(uint4*)(Kh + row * SQ + seg) = khi;
            *(uint4*)(Kl + row * SQ + seg) = klo;
            *(uint4*)(Vh + row * SV + seg) = vhi;
            *(uint4*)(Vl + row * SV + seg) = vlo;
        }
        if (tid < 64) pads[tid] = padb[kt * 64 + tid] ? -1e30f : 0.f;
        __syncthreads();

        float Sacc[4][4];
#pragma unroll
        for (int nt = 0; nt < 4; ++nt)
#pragma unroll
            for (int q = 0; q < 4; ++q) Sacc[nt][q] = 0.f;

#pragma unroll
        for (int ks = 0; ks < 8; ++ks) {
            uint32_t ah[4], al[4];
            ldsm_x4(qh_b + 32u * ks, ah);
            ldsm_x4(ql_b + 32u * ks, al);
            uint32_t bhf[2][4], blf[2][4];
#pragma unroll
            for (int p = 0; p < 2; ++p) {
                ldsm_x4(kh_b + p * ntp_step + 32u * ks, bhf[p]);
                ldsm_x4(kl_b + p * ntp_step + 32u * ks, blf[p]);
            }
#pragma unroll
            for (int nt = 0; nt < 4; ++nt) {
                const uint32_t bh0 = bhf[nt >> 1][(nt & 1) << 1];
                const uint32_t bh1 = bhf[nt >> 1][((nt & 1) << 1) + 1];
                const uint32_t bl0 = blf[nt >> 1][(nt & 1) << 1];
                const uint32_t bl1 = blf[nt >> 1][((nt & 1) << 1) + 1];
                mma_tf32(Sacc[nt], ah, bh0, bh1);
                mma_tf32(Sacc[nt], ah, bl0, bl1);
                mma_tf32(Sacc[nt], al, bh0, bh1);
            }
        }

        const int gi0 = qt * 64 + row0;
        const int gi1 = gi0 + 8;
        float mx0 = -1e30f, mx1 = -1e30f;
#pragma unroll
        for (int nt = 0; nt < 4; ++nt) {
            const int jl = 32 * wk + 8 * nt + 2 * c;
            const int gj0 = kt * 64 + jl, gj1 = gj0 + 1;
            const float pd0 = pads[jl], pd1 = pads[jl + 1];
            float s;
            s = Sacc[nt][0] + slope * (float)(gj0 - gi0) + pd0;
            if (gj0 > gi0 || gj0 < gi0 - WINDOW) s = -1e30f;
            Sacc[nt][0] = s; mx0 = fmaxf(mx0, s);
            s = Sacc[nt][1] + slope * (float)(gj1 - gi0) + pd1;
            if (gj1 > gi0 || gj1 < gi0 - WINDOW) s = -1e30f;
            Sacc[nt][1] = s; mx0 = fmaxf(mx0, s);
            s = Sacc[nt][2] + slope * (float)(gj0 - gi1) + pd0;
            if (gj0 > gi1 || gj0 < gi1 - WINDOW) s = -1e30f;
            Sacc[nt][2] = s; mx1 = fmaxf(mx1, s);
            s = Sacc[nt][3] + slope * (float)(gj1 - gi1) + pd1;
            if (gj1 > gi1 || gj1 < gi1 - WINDOW) s = -1e30f;
            Sacc[nt][3] = s; mx1 = fmaxf(mx1, s);
        }
        mx0 = fmaxf(mx0, __shfl_xor_sync(0xffffffffu, mx0, 1));
        mx0 = fmaxf(mx0, __shfl_xor_sync(0xffffffffu, mx0, 2));
        mx1 = fmaxf(mx1, __shfl_xor_sync(0xffffffffu, mx1, 1));
        mx1 = fmaxf(mx1, __shfl_xor_sync(0xffffffffu, mx1, 2));
        if (c == 0) { red[row0][wk] = mx0; red[row0 + 8][wk] = mx1; }
        __syncthreads();

        if (tid < 64) {
            const float mt = fmaxf(red[tid][0], red[tid][1]);
            const float mo = m_s[tid];
            const float mn = fmaxf(mo, mt);
            const float sc = __expf(mo - mn);
            m_s[tid] = mn; sc_s[tid] = sc; l_s[tid] *= sc;
        }
        __syncthreads();

        const float mn0 = m_s[row0], mn1 = m_s[row0 + 8];
        const float sc0 = sc_s[row0], sc1 = sc_s[row0 + 8];
        float rs0 = 0.f, rs1 = 0.f;
#pragma unroll
        for (int nt = 0; nt < 4; ++nt) {
            const int jl = 32 * wk + 8 * nt + 2 * c;
            float p0 = (Sacc[nt][0] < -1e29f) ? 0.f : __expf(Sacc[nt][0] - mn0);
            float p1 = (Sacc[nt][1] < -1e29f) ? 0.f : __expf(Sacc[nt][1] - mn0);
            float p2 = (Sacc[nt][2] < -1e29f) ? 0.f : __expf(Sacc[nt][2] - mn1);
            float p3 = (Sacc[nt][3] < -1e29f) ? 0.f : __expf(Sacc[nt][3] - mn1);
            rs0 += p0 + p1; rs1 += p2 + p3;
            uint2 hi, lo;
            split_tf32(p0, hi.x, lo.x); split_tf32(p1, hi.y, lo.y);
            *(uint2*)(Kh + row0 * SQ + jl) = hi;
            *(uint2*)(Kl + row0 * SQ + jl) = lo;
            split_tf32(p2, hi.x, lo.x); split_tf32(p3, hi.y, lo.y);
            *(uint2*)(Kh + (row0 + 8) * SQ + jl) = hi;
            *(uint2*)(Kl + (row0 + 8) * SQ + jl) = lo;
            Oacc[nt][0] *= sc0; Oacc[nt][1] *= sc0;
            Oacc[nt][2] *= sc1; Oacc[nt][3] *= sc1;
        }
        rs0 += __shfl_xor_sync(0xffffffffu, rs0, 1);
        rs0 += __shfl_xor_sync(0xffffffffu, rs0, 2);
        rs1 += __shfl_xor_sync(0xffffffffu, rs1, 1);
        rs1 += __shfl_xor_sync(0xffffffffu, rs1, 2);
        if (c == 0) { red[row0][wk] = rs0; red[row0 + 8][wk] = rs1; }
        __syncthreads();

        if (tid < 64) l_s[tid] += red[tid][0] + red[tid][1];

#pragma unroll
        for (int ks = 0; ks < 8; ++ks) {
            uint32_t ah[4], al[4];
            ldsm_x4(ph_b + 32u * ks, ah);
            ldsm_x4(pl_b + 32u * ks, al);
#pragma unroll
            for (int nt = 0; nt < 4; ++nt) {
                const int bbase = (c + 8 * ks) * SV + 32 * wk + 8 * nt + r;
                const uint32_t bh0 = Vh[bbase], bh1 = Vh[bbase + 4 * SV];
                const uint32_t bl0 = Vl[bbase], bl1 = Vl[bbase + 4 * SV];
                mma_tf32(Oacc[nt], ah, bh0, bh1);
                mma_tf32(Oacc[nt], ah, bl0, bl1);
                mma_tf32(Oacc[nt], al, bh0, bh1);
            }
        }
    }
    __syncthreads();

    const float inv0 = 1.f / l_s[row0];
    const float inv1 = 1.f / l_s[row0 + 8];
    const int gi0 = qt * 64 + row0;
    float* Ob = O + ((size_t)b * SEQ_L + gi0) * D_MODEL + h * HEAD_DIM;
#pragma unroll
    for (int nt = 0; nt < 4; ++nt) {
        const int dcol = 32 * wk + 8 * nt + 2 * c;
        *(float2*)(Ob + dcol) =
            make_float2(Oacc[nt][0] * inv0, Oacc[nt][1] * inv0);
        *(float2*)(Ob + 8 * D_MODEL + dcol) =
            make_float2(Oacc[nt][2] * inv1, Oacc[nt][3] * inv1);
    }
}

// ---------------------------------------------------------------------------
extern "C" void kernel_launch(void* const* d_in, const int* in_sizes, int n_in,
                              void* d_out, int out_size)
{
    const float* x  = (const float*)d_in[0];
    const unsigned char* pad = (const unsigned char*)d_in[1];
    const float* Wq = (const float*)d_in[2];
    const float* bq = (const float*)d_in[3];
    const float* Wk = (const float*)d_in[4];
    const float* bk = (const float*)d_in[5];
    const float* Wv = (const float*)d_in[6];
    const float* bv = (const float*)d_in[7];
    const float* Wo = (const float*)d_in[8];
    const float* bo = (const float*)d_in[9];
    float* out = (float*)d_out;

    float *q, *k, *v, *att;
    cudaGetSymbolAddress((void**)&q,   g_q);
    cudaGetSymbolAddress((void**)&k,   g_k);
    cudaGetSymbolAddress((void**)&v,   g_v);
    cudaGetSymbolAddress((void**)&att, g_att);

    cudaFuncSetAttribute(attn_alibi_mma,
                         cudaFuncAttributeMaxDynamicSharedMemorySize,
                         ATTN_SMEM_BYTES);

    const int M = BATCH * SEQ_L;              // 8192
    dim3 qkv_grid(D_MODEL / 128, M / 128, 3); // (8, 64, 3)
    gemm_tf32_db<<<qkv_grid, 256>>>(x, Wq, Wk, Wv, bq, bk, bv,
                                    q, k, v, M, D_MODEL, D_MODEL);

    dim3 agrid(SEQ_L / 64, BATCH * N_HEADS);  // (32, 64)
    attn_alibi_mma<<<agrid, 256, ATTN_SMEM_BYTES>>>(q, k, v, pad, att);

    dim3 o_grid(D_MODEL / 128, M / 128, 1);
    gemm_tf32_db<<<o_grid, 256>>>(att, Wo, Wo, Wo, bo, bo, bo,
                                  out, out, out, M, D_MODEL, D_MODEL);
}

// round 8
// speedup vs baseline: 2.7478x; 1.1732x over previous
#include <cuda_runtime.h>
#include <cuda_bf16.h>
#include <cstdint>

#define D_MODEL  1024
#define N_HEADS  16
#define HEAD_DIM 64
#define SEQ_L    2048
#define BATCH    4
#define WINDOW   512

#define MTOT (BATCH * SEQ_L)          // 8192

__device__ float g_q[MTOT * D_MODEL];
__device__ float g_k[MTOT * D_MODEL];
__device__ float g_v[MTOT * D_MODEL];
__device__ float g_att[MTOT * D_MODEL];
__device__ float g_xr[MTOT * D_MODEL];          // pre-rounded x
__device__ float g_wr[4 * D_MODEL * D_MODEL];   // pre-rounded Wq,Wk,Wv,Wo

__device__ __forceinline__ uint32_t f2tf32(float f) {
    uint32_t u;
    asm("cvt.rna.tf32.f32 %0, %1;" : "=r"(u) : "f"(f));
    return u;
}
__device__ __forceinline__ void mma_tf32(float* d, const uint32_t* a,
                                         uint32_t b0, uint32_t b1) {
    asm volatile(
        "mma.sync.aligned.m16n8k8.row.col.f32.tf32.tf32.f32 "
        "{%0,%1,%2,%3}, {%4,%5,%6,%7}, {%8,%9}, {%0,%1,%2,%3};"
        : "+f"(d[0]), "+f"(d[1]), "+f"(d[2]), "+f"(d[3])
        : "r"(a[0]), "r"(a[1]), "r"(a[2]), "r"(a[3]), "r"(b0), "r"(b1));
}
__device__ __forceinline__ void mma_bf16(float* d, const uint32_t* a,
                                         uint32_t b0, uint32_t b1) {
    asm volatile(
        "mma.sync.aligned.m16n8k16.row.col.f32.bf16.bf16.f32 "
        "{%0,%1,%2,%3}, {%4,%5,%6,%7}, {%8,%9}, {%0,%1,%2,%3};"
        : "+f"(d[0]), "+f"(d[1]), "+f"(d[2]), "+f"(d[3])
        : "r"(a[0]), "r"(a[1]), "r"(a[2]), "r"(a[3]), "r"(b0), "r"(b1));
}
__device__ __forceinline__ uint32_t smem_u32(const void* p) {
    uint32_t a;
    asm("{ .reg .u64 t; cvta.to.shared.u64 t, %1; cvt.u32.u64 %0, t; }"
        : "=r"(a) : "l"(p));
    return a;
}
__device__ __forceinline__ void ldsm_x4(uint32_t addr, uint32_t* r) {
    asm volatile(
        "ldmatrix.sync.aligned.m8n8.x4.shared.b16 {%0,%1,%2,%3}, [%4];"
        : "=r"(r[0]), "=r"(r[1]), "=r"(r[2]), "=r"(r[3]) : "r"(addr));
}
__device__ __forceinline__ void ldsm_x4_t(uint32_t addr, uint32_t* r) {
    asm volatile(
        "ldmatrix.sync.aligned.m8n8.x4.trans.shared.b16 {%0,%1,%2,%3}, [%4];"
        : "=r"(r[0]), "=r"(r[1]), "=r"(r[2]), "=r"(r[3]) : "r"(addr));
}
// split (e0,e1) into packed bf16x2 hi and lo (residual) words; lo half = e0
__device__ __forceinline__ void split_pair(float e0, float e1,
                                           uint32_t& h, uint32_t& l) {
    __nv_bfloat16 b0 = __float2bfloat16_rn(e0), b1 = __float2bfloat16_rn(e1);
    h = ((uint32_t)__bfloat16_as_ushort(b1) << 16) | __bfloat16_as_ushort(b0);
    float r0 = e0 - __bfloat162float(b0), r1 = e1 - __bfloat162float(b1);
    __nv_bfloat16 c0 = __float2bfloat16_rn(r0), c1 = __float2bfloat16_rn(r1);
    l = ((uint32_t)__bfloat16_as_ushort(c1) << 16) | __bfloat16_as_ushort(c0);
}

#define CP_ASYNC16(dst, src) \
    asm volatile("cp.async.cg.shared.global [%0], [%1], 16;" \
                 :: "r"(dst), "l"(src))
#define CP_COMMIT() asm volatile("cp.async.commit_group;")
#define CP_WAIT1()  asm volatile("cp.async.wait_group 1;" ::: "memory")

// ---------------------------------------------------------------------------
// Pre-round pass: out[i] = tf32_rna(in[i]) as fp32 bits.
// ---------------------------------------------------------------------------
__global__ void round_tf32_kernel(const float4* __restrict__ in,
                                  float4* __restrict__ out, int n4)
{
    const int i = blockIdx.x * blockDim.x + threadIdx.x;
    if (i < n4) {
        float4 v = in[i];
        float4 o;
        o.x = __uint_as_float(f2tf32(v.x));
        o.y = __uint_as_float(f2tf32(v.y));
        o.z = __uint_as_float(f2tf32(v.z));
        o.w = __uint_as_float(f2tf32(v.w));
        out[i] = o;
    }
}

// ---------------------------------------------------------------------------
// tf32 GEMM, cp.async double-buffer (inputs pre-rounded; no cvt/LDG/STS).
// C[m][n] = sum_k A[m][k]*W[n][k] + bias[n].  blockIdx.z selects (W,b,C).
// ---------------------------------------------------------------------------
__global__ __launch_bounds__(256, 2) void gemm_tf32_cp(
    const float* __restrict__ A, const float* __restrict__ Wbase,
    size_t wstride,
    const float* __restrict__ b0, const float* __restrict__ b1,
    const float* __restrict__ b2,
    float* __restrict__ C0, float* __restrict__ C1, float* __restrict__ C2,
    int M, int N, int K)
{
    __shared__ uint32_t As[2][128 * 32];
    __shared__ uint32_t Bs[2][128 * 32];

    const int z = blockIdx.z;
    const float* W    = Wbase + (size_t)z * wstride;
    const float* bias = (z == 0) ? b0 : (z == 1) ? b1 : b2;
    float*       C    = (z == 0) ? C0 : (z == 1) ? C1 : C2;

    const int tid    = threadIdx.x;
    const int warpId = tid >> 5;
    const int lane   = tid & 31;
    const int r      = lane >> 2;
    const int c      = lane & 3;
    const int warpM  = (warpId >> 2) * 64;
    const int warpN  = (warpId & 3) * 32;
    const int m0     = blockIdx.y * 128;
    const int n0     = blockIdx.x * 128;

    const int gRow = tid >> 1;
    const int gK   = (tid & 1) * 16;
    const float* Ag = A + (size_t)(m0 + gRow) * K + gK;
    const float* Wg = W + (size_t)(n0 + gRow) * K + gK;
    const int swr   = (gRow & 7) << 2;

    uint32_t soffb[4];
#pragma unroll
    for (int j = 0; j < 4; ++j)
        soffb[j] = (uint32_t)(gRow * 32 + ((gK + 4 * j) ^ swr)) * 4;

    const uint32_t asb[2] = { smem_u32(As[0]), smem_u32(As[1]) };
    const uint32_t bsb[2] = { smem_u32(Bs[0]), smem_u32(Bs[1]) };

    // ldmatrix per-lane addressing
    const int lrow8 = lane & 7;
    const int tsel  = lane >> 3;
    const int aRow  = warpM + ((tsel & 1) << 3) + lrow8;
    const int aCa   = tsel >> 1;
    const int bRow  = warpN + ((tsel >> 1) << 3) + lrow8;
    const int bCa   = tsel & 1;

    float acc[4][4][4];
#pragma unroll
    for (int mt = 0; mt < 4; ++mt)
#pragma unroll
        for (int nt = 0; nt < 4; ++nt)
#pragma unroll
            for (int q = 0; q < 4; ++q) acc[mt][nt][q] = 0.f;

    // preload stage 0
#pragma unroll
    for (int j = 0; j < 4; ++j) {
        CP_ASYNC16(asb[0] + soffb[j], Ag + 4 * j);
        CP_ASYNC16(bsb[0] + soffb[j], Wg + 4 * j);
    }
    CP_COMMIT();

    int st = 0;
    for (int k0 = 0; k0 < K; k0 += 32) {
        if (k0 + 32 < K) {
            const float* An = Ag + k0 + 32;
            const float* Wn = Wg + k0 + 32;
#pragma unroll
            for (int j = 0; j < 4; ++j) {
                CP_ASYNC16(asb[st ^ 1] + soffb[j], An + 4 * j);
                CP_ASYNC16(bsb[st ^ 1] + soffb[j], Wn + 4 * j);
            }
        }
        CP_COMMIT();
        CP_WAIT1();
        __syncthreads();

        const uint32_t a_s = asb[st], b_s = bsb[st];
#pragma unroll
        for (int ks = 0; ks < 4; ++ks) {
            uint32_t af[4][4];
            const uint32_t aChunk = (uint32_t)((2 * ks + aCa) ^ lrow8) << 4;
#pragma unroll
            for (int mt = 0; mt < 4; ++mt)
                ldsm_x4(a_s + ((uint32_t)(aRow + 16 * mt) << 7) + aChunk, af[mt]);

            uint32_t bf[2][4];
            const uint32_t bChunk = (uint32_t)((2 * ks + bCa) ^ lrow8) << 4;
#pragma unroll
            for (int p = 0; p < 2; ++p)
                ldsm_x4(b_s + ((uint32_t)(bRow + 16 * p) << 7) + bChunk, bf[p]);

#pragma unroll
            for (int nt = 0; nt < 4; ++nt) {
                const uint32_t bb0 = bf[nt >> 1][(nt & 1) << 1];
                const uint32_t bb1 = bf[nt >> 1][((nt & 1) << 1) + 1];
#pragma unroll
                for (int mt = 0; mt < 4; ++mt)
                    mma_tf32(acc[mt][nt], af[mt], bb0, bb1);
            }
        }
        __syncthreads();
        st ^= 1;
    }

#pragma unroll
    for (int nt = 0; nt < 4; ++nt) {
        const int col = n0 + warpN + 8 * nt + 2 * c;
        const float2 bv = *(const float2*)&bias[col];
#pragma unroll
        for (int mt = 0; mt < 4; ++mt) {
            const int row = m0 + warpM + 16 * mt + r;
            float2 o0 = make_float2(acc[mt][nt][0] + bv.x, acc[mt][nt][1] + bv.y);
            float2 o1 = make_float2(acc[mt][nt][2] + bv.x, acc[mt][nt][3] + bv.y);
            *(float2*)&C[(size_t)row * N + col]       = o0;
            *(float2*)&C[(size_t)(row + 8) * N + col] = o1;
        }
    }
}

// ---------------------------------------------------------------------------
// Flash attention, bf16x2 (3-term split) with m16n8k16 mma.
// Tiles stored as bf16 hi/lo planes, 64 rows x 128B, SW128 XOR swizzle:
//   addr = row*128 + ((chunk ^ (row&7))<<4) + (elt&7)*2
// Q[q][d], K[key][d] (B-frags non-trans), V[key][d] (B-frags via ldmatrix.trans),
// P[q][key] written into the K planes. Output written tf32-rounded for O-proj.
// ---------------------------------------------------------------------------
#define ATTN_SMEM_BYTES (6 * 64 * 128)   // 48 KB

__global__ __launch_bounds__(256) void attn_alibi_bf16(
    const float* __restrict__ Q, const float* __restrict__ K,
    const float* __restrict__ V, const unsigned char* __restrict__ pad,
    float* __restrict__ O)
{
    const int qt = blockIdx.x;
    const int bh = blockIdx.y;
    const int b  = bh >> 4;
    const int h  = bh & 15;

    extern __shared__ char smc[];
    char* Qh = smc;
    char* Ql = Qh + 8192;
    char* Kh = Ql + 8192;    // also P hi
    char* Kl = Kh + 8192;    // also P lo
    char* Vh = Kl + 8192;
    char* Vl = Vh + 8192;

    __shared__ float red[64][2];
    __shared__ float m_s[64], l_s[64], sc_s[64], pads[64];

    const int tid  = threadIdx.x;
    const int warp = tid >> 5;
    const int lane = tid & 31;
    const int r    = lane >> 2;
    const int c    = lane & 3;
    const int wq   = warp >> 1;
    const int wk   = warp & 1;

    const int lrow8 = lane & 7;
    const int tsel  = lane >> 3;

    // A-frag geometry (Q and P): rows 16wq.., chunks 2ks + (tsel>>1)
    const int aRow = 16 * wq + ((tsel & 1) << 3) + lrow8;
    const int aCa  = tsel >> 1;
    const int aR7  = aRow & 7;
    const uint32_t qh_b = smem_u32(Qh) + (uint32_t)aRow * 128;
    const uint32_t ql_b = smem_u32(Ql) + (uint32_t)aRow * 128;
    const uint32_t ph_b = smem_u32(Kh) + (uint32_t)aRow * 128;
    const uint32_t pl_b = smem_u32(Kl) + (uint32_t)aRow * 128;

    // K B-frag geometry: rows 32wk + 16p + .., chunks 2ks + (tsel&1)
    const int kRow = 32 * wk + ((tsel >> 1) << 3) + lrow8;
    const int kCa  = tsel & 1;
    const int kR7  = kRow & 7;
    const uint32_t kh_b = smem_u32(Kh) + (uint32_t)kRow * 128;
    const uint32_t kl_b = smem_u32(Kl) + (uint32_t)kRow * 128;

    // V trans B-frag geometry: k-rows 16ks + ((tsel&1)<<3)+lrow8,
    // d-chunks 4wk + 2p + (tsel>>1)
    const int vRow = ((tsel & 1) << 3) + lrow8;
    const int vCa  = 4 * wk + (tsel >> 1);
    const int vR7  = vRow & 7;
    const uint32_t vh_b = smem_u32(Vh) + (uint32_t)vRow * 128;
    const uint32_t vl_b = smem_u32(Vl) + (uint32_t)vRow * 128;

    const float slope = exp2f(-0.5f * (float)(h + 1));

    const float* Qb = Q + ((size_t)b * SEQ_L) * D_MODEL + h * HEAD_DIM;
    const float* Kb = K + ((size_t)b * SEQ_L) * D_MODEL + h * HEAD_DIM;
    const float* Vb = V + ((size_t)b * SEQ_L) * D_MODEL + h * HEAD_DIM;
    const unsigned char* padb = pad + (size_t)b * SEQ_L;

    // loader geometry: row = tid>>2 (0..63), 16 elts from d0=(tid&3)*16
    const int ldRow = tid >> 2;
    const int ldC0  = (tid & 3) * 2;
    const uint32_t off0 = (uint32_t)ldRow * 128 +
                          ((uint32_t)(ldC0 ^ (ldRow & 7)) << 4);
    const uint32_t off1 = (uint32_t)ldRow * 128 +
                          ((uint32_t)((ldC0 + 1) ^ (ldRow & 7)) << 4);
    const int ldD0 = (tid & 3) * 16;

    // ---- load Q tile (scaled by 0.125) ----
    {
        const float* src = Qb + (size_t)(qt * 64 + ldRow) * D_MODEL + ldD0;
        uint32_t hw[8], lw[8];
#pragma unroll
        for (int j = 0; j < 4; ++j) {
            float4 v = *(const float4*)(src + 4 * j);
            split_pair(v.x * 0.125f, v.y * 0.125f, hw[2 * j], lw[2 * j]);
            split_pair(v.z * 0.125f, v.w * 0.125f, hw[2 * j + 1], lw[2 * j + 1]);
        }
        *(uint4*)(Qh + off0) = make_uint4(hw[0], hw[1], hw[2], hw[3]);
        *(uint4*)(Qh + off1) = make_uint4(hw[4], hw[5], hw[6], hw[7]);
        *(uint4*)(Ql + off0) = make_uint4(lw[0], lw[1], lw[2], lw[3]);
        *(uint4*)(Ql + off1) = make_uint4(lw[4], lw[5], lw[6], lw[7]);
    }
    if (tid < 64) { m_s[tid] = -1e30f; l_s[tid] = 0.f; }

    float Oacc[4][4];
#pragma unroll
    for (int nt = 0; nt < 4; ++nt)
#pragma unroll
        for (int q = 0; q < 4; ++q) Oacc[nt][q] = 0.f;

    const int row0 = 16 * wq + r;
    const int kt_lo = (qt >= 8) ? (qt - 8) : 0;

    for (int kt = kt_lo; kt <= qt; ++kt) {
        __syncthreads();
        // ---- load K,V tiles ----
        {
            const float* ksrc = Kb + (size_t)(kt * 64 + ldRow) * D_MODEL + ldD0;
            const float* vsrc = Vb + (size_t)(kt * 64 + ldRow) * D_MODEL + ldD0;
            uint32_t hw[8], lw[8];
#pragma unroll
            for (int j = 0; j < 4; ++j) {
                float4 v = *(const float4*)(ksrc + 4 * j);
                split_pair(v.x, v.y, hw[2 * j], lw[2 * j]);
                split_pair(v.z, v.w, hw[2 * j + 1], lw[2 * j + 1]);
            }
            *(uint4*)(Kh + off0) = make_uint4(hw[0], hw[1], hw[2], hw[3]);
            *(uint4*)(Kh + off1) = make_uint4(hw[4], hw[5], hw[6], hw[7]);
            *(uint4*)(Kl + off0) = make_uint4(lw[0], lw[1], lw[2], lw[3]);
            *(uint4*)(Kl + off1) = make_uint4(lw[4], lw[5], lw[6], lw[7]);
#pragma unroll
            for (int j = 0; j < 4; ++j) {
                float4 v = *(const float4*)(vsrc + 4 * j);
                split_pair(v.x, v.y, hw[2 * j], lw[2 * j]);
                split_pair(v.z, v.w, hw[2 * j + 1], lw[2 * j + 1]);
            }
            *(uint4*)(Vh + off0) = make_uint4(hw[0], hw[1], hw[2], hw[3]);
            *(uint4*)(Vh + off1) = make_uint4(hw[4], hw[5], hw[6], hw[7]);
            *(uint4*)(Vl + off0) = make_uint4(lw[0], lw[1], lw[2], lw[3]);
            *(uint4*)(Vl + off1) = make_uint4(lw[4], lw[5], lw[6], lw[7]);
        }
        if (tid < 64) pads[tid] = padb[kt * 64 + tid] ? -1e30f : 0.f;
        __syncthreads();

        // ---- S = Q.K^T (4 k16 steps) ----
        float Sacc[4][4];
#pragma unroll
        for (int nt = 0; nt < 4; ++nt)
#pragma unroll
            for (int q = 0; q < 4; ++q) Sacc[nt][q] = 0.f;

#pragma unroll
        for (int ks = 0; ks < 4; ++ks) {
            uint32_t ah[4], al[4];
            const uint32_t axo = ((uint32_t)((2 * ks + aCa) ^ aR7) << 4);
            ldsm_x4(qh_b + axo, ah);
            ldsm_x4(ql_b + axo, al);
            uint32_t bhf[2][4], blf[2][4];
            const uint32_t kxo = ((uint32_t)((2 * ks + kCa) ^ kR7) << 4);
#pragma unroll
            for (int p = 0; p < 2; ++p) {
                ldsm_x4(kh_b + (uint32_t)p * 2048 + kxo, bhf[p]);
                ldsm_x4(kl_b + (uint32_t)p * 2048 + kxo, blf[p]);
            }
#pragma unroll
            for (int nt = 0; nt < 4; ++nt) {
                const uint32_t bh0 = bhf[nt >> 1][(nt & 1) << 1];
                const uint32_t bh1 = bhf[nt >> 1][((nt & 1) << 1) + 1];
                const uint32_t bl0 = blf[nt >> 1][(nt & 1) << 1];
                const uint32_t bl1 = blf[nt >> 1][((nt & 1) << 1) + 1];
                mma_bf16(Sacc[nt], ah, bh0, bh1);
                mma_bf16(Sacc[nt], ah, bl0, bl1);
                mma_bf16(Sacc[nt], al, bh0, bh1);
            }
        }

        // ---- mask + ALiBi + row max ----
        const int gi0 = qt * 64 + row0;
        const int gi1 = gi0 + 8;
        float mx0 = -1e30f, mx1 = -1e30f;
#pragma unroll
        for (int nt = 0; nt < 4; ++nt) {
            const int jl = 32 * wk + 8 * nt + 2 * c;
            const int gj0 = kt * 64 + jl, gj1 = gj0 + 1;
            const float pd0 = pads[jl], pd1 = pads[jl + 1];
            float s;
            s = Sacc[nt][0] + slope * (float)(gj0 - gi0) + pd0;
            if (gj0 > gi0 || gj0 < gi0 - WINDOW) s = -1e30f;
            Sacc[nt][0] = s; mx0 = fmaxf(mx0, s);
            s = Sacc[nt][1] + slope * (float)(gj1 - gi0) + pd1;
            if (gj1 > gi0 || gj1 < gi0 - WINDOW) s = -1e30f;
            Sacc[nt][1] = s; mx0 = fmaxf(mx0, s);
            s = Sacc[nt][2] + slope * (float)(gj0 - gi1) + pd0;
            if (gj0 > gi1 || gj0 < gi1 - WINDOW) s = -1e30f;
            Sacc[nt][2] = s; mx1 = fmaxf(mx1, s);
            s = Sacc[nt][3] + slope * (float)(gj1 - gi1) + pd1;
            if (gj1 > gi1 || gj1 < gi1 - WINDOW) s = -1e30f;
            Sacc[nt][3] = s; mx1 = fmaxf(mx1, s);
        }
        mx0 = fmaxf(mx0, __shfl_xor_sync(0xffffffffu, mx0, 1));
        mx0 = fmaxf(mx0, __shfl_xor_sync(0xffffffffu, mx0, 2));
        mx1 = fmaxf(mx1, __shfl_xor_sync(0xffffffffu, mx1, 1));
        mx1 = fmaxf(mx1, __shfl_xor_sync(0xffffffffu, mx1, 2));
        if (c == 0) { red[row0][wk] = mx0; red[row0 + 8][wk] = mx1; }
        __syncthreads();

        if (tid < 64) {
            const float mt = fmaxf(red[tid][0], red[tid][1]);
            const float mo = m_s[tid];
            const float mn = fmaxf(mo, mt);
            const float sc = __expf(mo - mn);
            m_s[tid] = mn; sc_s[tid] = sc; l_s[tid] *= sc;
        }
        __syncthreads();

        // ---- P = exp(S-m); write bf16x2 P into K planes; rescale O ----
        const float mn0 = m_s[row0], mn1 = m_s[row0 + 8];
        const float sc0 = sc_s[row0], sc1 = sc_s[row0 + 8];
        float rs0 = 0.f, rs1 = 0.f;
        const uint32_t prow0 = (uint32_t)row0 * 128;
        const uint32_t prow1 = (uint32_t)(row0 + 8) * 128;
        const uint32_t pxr = (uint32_t)(row0 & 7);   // same for row0+8
#pragma unroll
        for (int nt = 0; nt < 4; ++nt) {
            const int jl = 32 * wk + 8 * nt + 2 * c;
            float p0 = (Sacc[nt][0] < -1e29f) ? 0.f : __expf(Sacc[nt][0] - mn0);
            float p1 = (Sacc[nt][1] < -1e29f) ? 0.f : __expf(Sacc[nt][1] - mn0);
            float p2 = (Sacc[nt][2] < -1e29f) ? 0.f : __expf(Sacc[nt][2] - mn1);
            float p3 = (Sacc[nt][3] < -1e29f) ? 0.f : __expf(Sacc[nt][3] - mn1);
            rs0 += p0 + p1; rs1 += p2 + p3;
            const uint32_t cxo = (((uint32_t)(4 * wk + nt) ^ pxr) << 4) + 4 * c;
            uint32_t ph, pl;
            split_pair(p0, p1, ph, pl);
            *(uint32_t*)(Kh + prow0 + cxo) = ph;
            *(uint32_t*)(Kl + prow0 + cxo) = pl;
            split_pair(p2, p3, ph, pl);
            *(uint32_t*)(Kh + prow1 + cxo) = ph;
            *(uint32_t*)(Kl + prow1 + cxo) = pl;
            Oacc[nt][0] *= sc0; Oacc[nt][1] *= sc0;
            Oacc[nt][2] *= sc1; Oacc[nt][3] *= sc1;
        }
        rs0 += __shfl_xor_sync(0xffffffffu, rs0, 1);
        rs0 += __shfl_xor_sync(0xffffffffu, rs0, 2);
        rs1 += __shfl_xor_sync(0xffffffffu, rs1, 1);
        rs1 += __shfl_xor_sync(0xffffffffu, rs1, 2);
        if (c == 0) { red[row0][wk] = rs0; red[row0 + 8][wk] = rs1; }
        __syncthreads();

        if (tid < 64) l_s[tid] += red[tid][0] + red[tid][1];

        // ---- O += P.V (4 k16 steps; V via ldmatrix.trans) ----
#pragma unroll
        for (int ks = 0; ks < 4; ++ks) {
            uint32_t ah[4], al[4];
            const uint32_t axo = ((uint32_t)((2 * ks + aCa) ^ aR7) << 4);
            ldsm_x4(ph_b + axo, ah);
            ldsm_x4(pl_b + axo, al);
            uint32_t bvh[2][4], bvl[2][4];
#pragma unroll
            for (int p = 0; p < 2; ++p) {
                const uint32_t vxo = (uint32_t)ks * 2048 +
                    (((uint32_t)(vCa + 2 * p) ^ vR7) << 4);
                ldsm_x4_t(vh_b + vxo, bvh[p]);
                ldsm_x4_t(vl_b + vxo, bvl[p]);
            }
#pragma unroll
            for (int nt = 0; nt < 4; ++nt) {
                const uint32_t bh0 = bvh[nt >> 1][(nt & 1) << 1];
                const uint32_t bh1 = bvh[nt >> 1][((nt & 1) << 1) + 1];
                const uint32_t bl0 = bvl[nt >> 1][(nt & 1) << 1];
                const uint32_t bl1 = bvl[nt >> 1][((nt & 1) << 1) + 1];
                mma_bf16(Oacc[nt], ah, bh0, bh1);
                mma_bf16(Oacc[nt], ah, bl0, bl1);
                mma_bf16(Oacc[nt], al, bh0, bh1);
            }
        }
    }
    __syncthreads();

    const float inv0 = 1.f / l_s[row0];
    const float inv1 = 1.f / l_s[row0 + 8];
    const int gi0 = qt * 64 + row0;
    float* Ob = O + ((size_t)b * SEQ_L + gi0) * D_MODEL + h * HEAD_DIM;
#pragma unroll
    for (int nt = 0; nt < 4; ++nt) {
        const int dcol = 32 * wk + 8 * nt + 2 * c;
        // write tf32-rounded (O-proj consumes via cp.async/mma directly)
        *(float2*)(Ob + dcol) = make_float2(
            __uint_as_float(f2tf32(Oacc[nt][0] * inv0)),
            __uint_as_float(f2tf32(Oacc[nt][1] * inv0)));
        *(float2*)(Ob + 8 * D_MODEL + dcol) = make_float2(
            __uint_as_float(f2tf32(Oacc[nt][2] * inv1)),
            __uint_as_float(f2tf32(Oacc[nt][3] * inv1)));
    }
}

// ---------------------------------------------------------------------------
extern "C" void kernel_launch(void* const* d_in, const int* in_sizes, int n_in,
                              void* d_out, int out_size)
{
    const float* x  = (const float*)d_in[0];
    const unsigned char* pad = (const unsigned char*)d_in[1];
    const float* Wq = (const float*)d_in[2];
    const float* bq = (const float*)d_in[3];
    const float* Wk = (const float*)d_in[4];
    const float* bk = (const float*)d_in[5];
    const float* Wv = (const float*)d_in[6];
    const float* bv = (const float*)d_in[7];
    const float* Wo = (const float*)d_in[8];
    const float* bo = (const float*)d_in[9];
    float* out = (float*)d_out;

    float *q, *k, *v, *att, *xr, *wr;
    cudaGetSymbolAddress((void**)&q,   g_q);
    cudaGetSymbolAddress((void**)&k,   g_k);
    cudaGetSymbolAddress((void**)&v,   g_v);
    cudaGetSymbolAddress((void**)&att, g_att);
    cudaGetSymbolAddress((void**)&xr,  g_xr);
    cudaGetSymbolAddress((void**)&wr,  g_wr);

    cudaFuncSetAttribute(attn_alibi_bf16,
                         cudaFuncAttributeMaxDynamicSharedMemorySize,
                         ATTN_SMEM_BYTES);

    const int WN = D_MODEL * D_MODEL;          // 1M elts per weight
    const int xn4 = MTOT * D_MODEL / 4;        // 2M float4
    const int wn4 = WN / 4;                    // 256K float4
    round_tf32_kernel<<<(xn4 + 255) / 256, 256>>>((const float4*)x,
                                                  (float4*)xr, xn4);
    round_tf32_kernel<<<(wn4 + 255) / 256, 256>>>((const float4*)Wq,
                                                  (float4*)(wr + 0 * WN), wn4);
    round_tf32_kernel<<<(wn4 + 255) / 256, 256>>>((const float4*)Wk,
                                                  (float4*)(wr + 1 * WN), wn4);
    round_tf32_kernel<<<(wn4 + 255) / 256, 256>>>((const float4*)Wv,
                                                  (float4*)(wr + 2 * WN), wn4);
    round_tf32_kernel<<<(wn4 + 255) / 256, 256>>>((const float4*)Wo,
                                                  (float4*)(wr + 3 * WN), wn4);

    dim3 qkv_grid(D_MODEL / 128, MTOT / 128, 3); // (8, 64, 3)
    gemm_tf32_cp<<<qkv_grid, 256>>>(xr, wr, (size_t)WN, bq, bk, bv,
                                    q, k, v, MTOT, D_MODEL, D_MODEL);

    dim3 agrid(SEQ_L / 64, BATCH * N_HEADS);   // (32, 64)
    attn_alibi_bf16<<<agrid, 256, ATTN_SMEM_BYTES>>>(q, k, v, pad, att);

    dim3 o_grid(D_MODEL / 128, MTOT / 128, 1);
    gemm_tf32_cp<<<o_grid, 256>>>(att, wr + 3 * WN, (size_t)0, bo, bo, bo,
                                  out, out, out, MTOT, D_MODEL, D_MODEL);
}